// round 5
// baseline (speedup 1.0000x reference)
#include <cuda_runtime.h>
#include <cuda_fp16.h>
#include <math.h>
#include <stdint.h>

#define VOCAB 32000
#define EMBED 512
#define KQD   512
#define VDIM  512
#define NB    2
#define SEQ   2048
#define NTOK  (NB * SEQ)

// ---------------- scratch (__device__ globals; no allocation allowed) -------
__device__ float g_h[NTOK * EMBED];
__device__ float g_Q[NTOK * KQD];
__device__ float g_K[NTOK * KQD];
__device__ float g_V[NTOK * VDIM];
__device__ float g_S[(size_t)NB * SEQ * SEQ];
__device__ float g_C[NTOK * VDIM];

struct GemmPtrs {
    const float* A[3];
    const float* B[3];
    float*       C[3];
};

// ---------------- stage 1: h = emb[x] + sinusoidal PE -----------------------
__global__ void embed_pe_kernel(const int* __restrict__ x,
                                const float* __restrict__ emb) {
    int tok = blockIdx.x;
    int s = tok & (SEQ - 1);
    const float* e = emb + (size_t)x[tok] * EMBED;
    float* o = g_h + (size_t)tok * EMBED;
    for (int i = threadIdx.x; i < EMBED; i += blockDim.x) {
        int j = i >> 1;
        float freq = expf((float)(2 * j) * (-9.210340371976184f / (float)EMBED));
        float ang = (float)s * freq;
        float pe = (i & 1) ? cosf(ang) : sinf(ang);
        o[i] = e[i] + pe;
    }
}

// ---------------- fp16 helpers ----------------------------------------------
__device__ __forceinline__ uint32_t h2u(__half2 h) {
    return *reinterpret_cast<uint32_t*>(&h);
}

__device__ __forceinline__ void mma_f16(float* acc, const uint32_t* a,
                                        const uint32_t* b) {
    asm("mma.sync.aligned.m16n8k16.row.col.f32.f16.f16.f32 "
        "{%0,%1,%2,%3}, {%4,%5,%6,%7}, {%8,%9}, {%0,%1,%2,%3};"
        : "+f"(acc[0]), "+f"(acc[1]), "+f"(acc[2]), "+f"(acc[3])
        : "r"(a[0]), "r"(a[1]), "r"(a[2]), "r"(a[3]), "r"(b[0]), "r"(b[1]));
}

// convert float4 (4 consecutive k) into 2 fp16x2 hi words (+ lo words if NPASS==3)
template <int NPASS>
__device__ __forceinline__ void cvt_store2(uint32_t* dh, uint32_t* dl, float4 v) {
    __half2 h0 = __floats2half2_rn(v.x, v.y);
    __half2 h1 = __floats2half2_rn(v.z, v.w);
    dh[0] = h2u(h0);
    dh[1] = h2u(h1);
    if (NPASS == 3) {
        __half2 l0 = __floats2half2_rn(v.x - __low2float(h0), v.y - __high2float(h0));
        __half2 l1 = __floats2half2_rn(v.z - __low2float(h1), v.w - __high2float(h1));
        dl[0] = h2u(l0);
        dl[1] = h2u(l1);
    }
}

// ---------------- unified fp16 tensor-core GEMM ------------------------------
// C[M,N] = scale * (A[M,K] @ op(B)) + bias
//   BNT=true : B is [N,K] row-major; BNT=false: B is [K,N] row-major.
//   NPASS=3: hi/lo fp16 error compensation (fp32-class); NPASS=1: plain fp16.
//   CAUSAL_OUT: skip n0 > m0+127 tiles. CAUSAL_K: k-loop only to m0+128.
// CTA 128x128, BK=16, double-buffered fp16x2 smem, 8 warps as 2(M) x 4(N).
// Smem layouts (uint32 words, each = 2 k-adjacent fp16):
//   A / BNT-B : [row][kpair] pad 12  -> fragment LDS conflict-free
//   NN-B      : [kpair][col] pad 136 -> fragment LDS conflict-free
template <int NPASS, bool BNT, bool CAUSAL_OUT, bool CAUSAL_K, bool BIAS, bool NXFAST>
__global__ __launch_bounds__(256)
void hgemm(GemmPtrs p, const float* __restrict__ bias,
           int M, int N, int K, float scale) {
    const int n0 = (NXFAST ? blockIdx.x : blockIdx.y) * 128;
    const int m0 = (NXFAST ? blockIdx.y : blockIdx.x) * 128;
    if (CAUSAL_OUT && n0 > m0 + 127) return;

    const float* __restrict__ A = p.A[blockIdx.z];
    const float* __restrict__ B = p.B[blockIdx.z];
    float* __restrict__ C       = p.C[blockIdx.z];

    const int kmax = CAUSAL_K ? ((m0 + 128 < K) ? m0 + 128 : K) : K;

    constexpr int AW = 12;                 // 8 kpair words + 4 pad
    constexpr int BR = BNT ? 128 : 8;      // rows of B smem
    constexpr int BW = BNT ? 12 : 136;     // row width (words)
    __shared__ uint32_t Ash[2][128][AW];
    __shared__ uint32_t Bsh[2][BR][BW];
    __shared__ uint32_t Asl[NPASS == 3 ? 2 : 1][NPASS == 3 ? 128 : 1][NPASS == 3 ? AW : 1];
    __shared__ uint32_t Bsl[NPASS == 3 ? 2 : 1][NPASS == 3 ? BR : 1][NPASS == 3 ? BW : 1];

    const int tid = threadIdx.x;
    const int lane = tid & 31;
    const int wid = tid >> 5;
    const int warpM = wid >> 2;
    const int warpN = wid & 3;
    const int qr = lane >> 2;
    const int qc = lane & 3;

    const int frow0 = tid >> 2;            // rows 0..63
    const int frow1 = (tid + 256) >> 2;    // rows 64..127
    const int fc4 = tid & 3;               // which float4 of the 16-k tile
    const int prn = tid >> 5;              // NN: k-pair row 0..7
    const int c4n = (tid & 31) * 4;        // NN: col 0..124

    float acc[4][4][4] = {};
    float4 av0, av1, bv0, bv1;

    // ---- prologue: global fetch k-tile 0 ----
    av0 = *(const float4*)&A[(size_t)(m0 + frow0) * K + fc4 * 4];
    av1 = *(const float4*)&A[(size_t)(m0 + frow1) * K + fc4 * 4];
    if (BNT) {
        bv0 = *(const float4*)&B[(size_t)(n0 + frow0) * K + fc4 * 4];
        bv1 = *(const float4*)&B[(size_t)(n0 + frow1) * K + fc4 * 4];
    } else {
        bv0 = *(const float4*)&B[(size_t)(2 * prn) * N + n0 + c4n];
        bv1 = *(const float4*)&B[(size_t)(2 * prn + 1) * N + n0 + c4n];
    }

    // ---- store k-tile 0 into buffer 0 ----
    {
        uint32_t *pl0 = nullptr, *pl1 = nullptr;
        if (NPASS == 3) { pl0 = &Asl[0][frow0][fc4 * 2]; pl1 = &Asl[0][frow1][fc4 * 2]; }
        cvt_store2<NPASS>(&Ash[0][frow0][fc4 * 2], pl0, av0);
        cvt_store2<NPASS>(&Ash[0][frow1][fc4 * 2], pl1, av1);
        if (BNT) {
            uint32_t *ql0 = nullptr, *ql1 = nullptr;
            if (NPASS == 3) {
                ql0 = &Bsl[0][frow0 % BR][(fc4 * 2) % BW];
                ql1 = &Bsl[0][frow1 % BR][(fc4 * 2) % BW];
            }
            cvt_store2<NPASS>(&Bsh[0][frow0 % BR][(fc4 * 2) % BW], ql0, bv0);
            cvt_store2<NPASS>(&Bsh[0][frow1 % BR][(fc4 * 2) % BW], ql1, bv1);
        } else {
            const float a0[4] = {bv0.x, bv0.y, bv0.z, bv0.w};
            const float a1[4] = {bv1.x, bv1.y, bv1.z, bv1.w};
            uint32_t wh[4], wl[4];
#pragma unroll
            for (int j = 0; j < 4; j++) {
                __half2 hh = __floats2half2_rn(a0[j], a1[j]);
                wh[j] = h2u(hh);
                if (NPASS == 3) {
                    __half2 ll = __floats2half2_rn(a0[j] - __low2float(hh),
                                                   a1[j] - __high2float(hh));
                    wl[j] = h2u(ll);
                }
            }
            *(uint4*)&Bsh[0][prn % BR][c4n % BW] = *(uint4*)wh;
            if (NPASS == 3) *(uint4*)&Bsl[0][prn % BR][c4n % BW] = *(uint4*)wl;
        }
    }
    __syncthreads();

    const int NIT = kmax / 16;
    for (int it = 0; it < NIT; it++) {
        const int cur = it & 1;
        // prefetch next k-tile into registers (overlaps compute)
        if (it + 1 < NIT) {
            const int k0 = (it + 1) * 16;
            av0 = *(const float4*)&A[(size_t)(m0 + frow0) * K + k0 + fc4 * 4];
            av1 = *(const float4*)&A[(size_t)(m0 + frow1) * K + k0 + fc4 * 4];
            if (BNT) {
                bv0 = *(const float4*)&B[(size_t)(n0 + frow0) * K + k0 + fc4 * 4];
                bv1 = *(const float4*)&B[(size_t)(n0 + frow1) * K + k0 + fc4 * 4];
            } else {
                bv0 = *(const float4*)&B[(size_t)(k0 + 2 * prn) * N + n0 + c4n];
                bv1 = *(const float4*)&B[(size_t)(k0 + 2 * prn + 1) * N + n0 + c4n];
            }
        }

        // ---- fragments: one m16n8k16 step consumes the whole 16-k tile ----
        uint32_t ah[4][4], al[4][4], bh[4][2], bl[4][2];
#pragma unroll
        for (int mt = 0; mt < 4; mt++) {
            const int r = warpM * 64 + mt * 16 + qr;
            ah[mt][0] = Ash[cur][r][qc];
            ah[mt][1] = Ash[cur][r + 8][qc];
            ah[mt][2] = Ash[cur][r][qc + 4];
            ah[mt][3] = Ash[cur][r + 8][qc + 4];
            if (NPASS == 3) {
                al[mt][0] = Asl[cur][r % 128][qc % AW];
                al[mt][1] = Asl[cur][(r + 8) % 128][qc % AW];
                al[mt][2] = Asl[cur][r % 128][(qc + 4) % AW];
                al[mt][3] = Asl[cur][(r + 8) % 128][(qc + 4) % AW];
            }
        }
#pragma unroll
        for (int nt = 0; nt < 4; nt++) {
            const int n = warpN * 32 + nt * 8 + qr;
            if (BNT) {
                bh[nt][0] = Bsh[cur][n % BR][qc % BW];
                bh[nt][1] = Bsh[cur][n % BR][(qc + 4) % BW];
                if (NPASS == 3) {
                    bl[nt][0] = Bsl[cur][n % BR][qc % BW];
                    bl[nt][1] = Bsl[cur][n % BR][(qc + 4) % BW];
                }
            } else {
                bh[nt][0] = Bsh[cur][qc % BR][n % BW];
                bh[nt][1] = Bsh[cur][(qc + 4) % BR][n % BW];
                if (NPASS == 3) {
                    bl[nt][0] = Bsl[cur][qc % BR][n % BW];
                    bl[nt][1] = Bsl[cur][(qc + 4) % BR][n % BW];
                }
            }
        }
#pragma unroll
        for (int mt = 0; mt < 4; mt++)
#pragma unroll
            for (int nt = 0; nt < 4; nt++) {
                mma_f16(acc[mt][nt], ah[mt], bh[nt]);
                if (NPASS == 3) {
                    mma_f16(acc[mt][nt], ah[mt], bl[nt]);
                    mma_f16(acc[mt][nt], al[mt], bh[nt]);
                }
            }
        __syncthreads();

        // ---- store the prefetched tile into the other buffer ----
        if (it + 1 < NIT) {
            const int nxt = cur ^ 1;
            uint32_t *pl0 = nullptr, *pl1 = nullptr;
            if (NPASS == 3) {
                pl0 = &Asl[nxt % 2][frow0][fc4 * 2];
                pl1 = &Asl[nxt % 2][frow1][fc4 * 2];
            }
            cvt_store2<NPASS>(&Ash[nxt][frow0][fc4 * 2], pl0, av0);
            cvt_store2<NPASS>(&Ash[nxt][frow1][fc4 * 2], pl1, av1);
            if (BNT) {
                uint32_t *ql0 = nullptr, *ql1 = nullptr;
                if (NPASS == 3) {
                    ql0 = &Bsl[nxt % 2][frow0 % BR][(fc4 * 2) % BW];
                    ql1 = &Bsl[nxt % 2][frow1 % BR][(fc4 * 2) % BW];
                }
                cvt_store2<NPASS>(&Bsh[nxt][frow0 % BR][(fc4 * 2) % BW], ql0, bv0);
                cvt_store2<NPASS>(&Bsh[nxt][frow1 % BR][(fc4 * 2) % BW], ql1, bv1);
            } else {
                const float a0[4] = {bv0.x, bv0.y, bv0.z, bv0.w};
                const float a1[4] = {bv1.x, bv1.y, bv1.z, bv1.w};
                uint32_t wh[4], wl[4];
#pragma unroll
                for (int j = 0; j < 4; j++) {
                    __half2 hh = __floats2half2_rn(a0[j], a1[j]);
                    wh[j] = h2u(hh);
                    if (NPASS == 3) {
                        __half2 ll = __floats2half2_rn(a0[j] - __low2float(hh),
                                                       a1[j] - __high2float(hh));
                        wl[j] = h2u(ll);
                    }
                }
                *(uint4*)&Bsh[nxt][prn % BR][c4n % BW] = *(uint4*)wh;
                if (NPASS == 3) *(uint4*)&Bsl[nxt % 2][prn % BR][c4n % BW] = *(uint4*)wl;
            }
            __syncthreads();
        }
    }

    // ---- epilogue ----
#pragma unroll
    for (int mt = 0; mt < 4; mt++) {
        const int r = m0 + warpM * 64 + mt * 16 + qr;
#pragma unroll
        for (int nt = 0; nt < 4; nt++) {
            const int c = n0 + warpN * 32 + nt * 8 + qc * 2;
            float2 bb = BIAS ? *(const float2*)&bias[c] : make_float2(0.f, 0.f);
            float2 v0, v1;
            v0.x = acc[mt][nt][0] * scale + bb.x;
            v0.y = acc[mt][nt][1] * scale + bb.y;
            v1.x = acc[mt][nt][2] * scale + bb.x;
            v1.y = acc[mt][nt][3] * scale + bb.y;
            *(float2*)&C[(size_t)r * N + c] = v0;
            *(float2*)&C[(size_t)(r + 8) * N + c] = v1;
        }
    }
}

// ---------------- stage 4: causal row softmax (in place on g_S) -------------
__global__ void softmax_causal_kernel() {
    int row = blockIdx.x;
    int b = row / SEQ;
    int q = row & (SEQ - 1);
    float* r = g_S + (size_t)b * SEQ * SEQ + (size_t)q * SEQ;
    const int len = q + 1;

    __shared__ float redm[8];
    __shared__ float reds[8];
    __shared__ float bc[2];

    float m = -INFINITY;
    for (int i = threadIdx.x; i < len; i += 256) m = fmaxf(m, r[i]);
#pragma unroll
    for (int o = 16; o; o >>= 1) m = fmaxf(m, __shfl_xor_sync(0xffffffffu, m, o));
    if ((threadIdx.x & 31) == 0) redm[threadIdx.x >> 5] = m;
    __syncthreads();
    if (threadIdx.x == 0) {
        float v = redm[0];
#pragma unroll
        for (int w = 1; w < 8; w++) v = fmaxf(v, redm[w]);
        bc[0] = v;
    }
    __syncthreads();
    const float rmax = bc[0];

    float s = 0.f;
    for (int i = threadIdx.x; i < len; i += 256) {
        float e = __expf(r[i] - rmax);
        r[i] = e;
        s += e;
    }
#pragma unroll
    for (int o = 16; o; o >>= 1) s += __shfl_xor_sync(0xffffffffu, s, o);
    if ((threadIdx.x & 31) == 0) reds[threadIdx.x >> 5] = s;
    __syncthreads();
    if (threadIdx.x == 0) {
        float v = reds[0];
#pragma unroll
        for (int w = 1; w < 8; w++) v += reds[w];
        bc[1] = 1.0f / v;
    }
    __syncthreads();
    const float inv = bc[1];

    for (int i = threadIdx.x; i < len; i += 256) r[i] *= inv;
    for (int i = len + threadIdx.x; i < SEQ; i += 256) r[i] = 0.f;
}

// ---------------- launch ----------------------------------------------------
extern "C" void kernel_launch(void* const* d_in, const int* in_sizes, int n_in,
                              void* d_out, int out_size) {
    const int*   x   = (const int*)d_in[0];
    const float* emb = (const float*)d_in[1];
    const float* Wq  = (const float*)d_in[2];
    const float* Wk  = (const float*)d_in[3];
    const float* Wv  = (const float*)d_in[4];
    const float* Wh  = (const float*)d_in[5];
    const float* bh  = (const float*)d_in[6];
    float* out = (float*)d_out;

    float *h, *Q, *K, *V, *S, *C;
    cudaGetSymbolAddress((void**)&h, g_h);
    cudaGetSymbolAddress((void**)&Q, g_Q);
    cudaGetSymbolAddress((void**)&K, g_K);
    cudaGetSymbolAddress((void**)&V, g_V);
    cudaGetSymbolAddress((void**)&S, g_S);
    cudaGetSymbolAddress((void**)&C, g_C);

    const float sscale = 22.627416997969522f;  // sqrt(512)
    const dim3 blk(256);

    // 1) embedding + positional encoding
    embed_pe_kernel<<<NTOK, 128>>>(x, emb);

    // 2) fused Q/K/V projections (3-pass fp16 compensation)
    {
        GemmPtrs p;
        p.A[0] = p.A[1] = p.A[2] = h;
        p.B[0] = Wq; p.B[1] = Wk; p.B[2] = Wv;
        p.C[0] = Q;  p.C[1] = K;  p.C[2] = V;
        hgemm<3, true, false, false, false, true>
            <<<dim3(KQD / 128, NTOK / 128, 3), blk>>>(p, nullptr, NTOK, KQD, EMBED, 1.f);
    }

    // 3) scores = sqrt(512) * Q K^T (3-pass fp16, causal tiles skipped)
    {
        GemmPtrs p;
        for (int b = 0; b < NB; b++) {
            p.A[b] = Q + (size_t)b * SEQ * KQD;
            p.B[b] = K + (size_t)b * SEQ * KQD;
            p.C[b] = S + (size_t)b * SEQ * SEQ;
        }
        p.A[2] = p.B[2] = p.C[2] = nullptr;
        hgemm<3, true, true, false, false, true>
            <<<dim3(SEQ / 128, SEQ / 128, NB), blk>>>(p, nullptr, SEQ, SEQ, KQD, sscale);
    }

    // 4) causal softmax in place
    softmax_causal_kernel<<<NTOK, 256>>>();

    // 5) ctx = attn @ V (3-pass fp16 NN, causal-k trimmed)
    {
        GemmPtrs p;
        for (int b = 0; b < NB; b++) {
            p.A[b] = S + (size_t)b * SEQ * SEQ;
            p.B[b] = V + (size_t)b * SEQ * VDIM;
            p.C[b] = C + (size_t)b * SEQ * VDIM;
        }
        p.A[2] = p.B[2] = p.C[2] = nullptr;
        hgemm<3, false, false, true, false, true>
            <<<dim3(VDIM / 128, SEQ / 128, NB), blk>>>(p, nullptr, SEQ, VDIM, SEQ, 1.f);
    }

    // 6) logits = ctx @ Wh^T + bh (single-pass fp16; m tiles on fast axis for L2)
    {
        GemmPtrs p;
        p.A[0] = C; p.B[0] = Wh; p.C[0] = out;
        p.A[1] = p.A[2] = p.B[1] = p.B[2] = nullptr;
        p.C[1] = p.C[2] = nullptr;
        hgemm<1, true, false, false, true, false>
            <<<dim3(NTOK / 128, VOCAB / 128, 1), blk>>>(p, bh, NTOK, VOCAB, VDIM, 1.f);
    }
}

// round 6
// speedup vs baseline: 1.2133x; 1.2133x over previous
#include <cuda_runtime.h>
#include <cuda_fp16.h>
#include <math.h>
#include <stdint.h>

#define VOCAB 32000
#define EMBED 512
#define KQD   512
#define VDIM  512
#define NB    2
#define SEQ   2048
#define NTOK  (NB * SEQ)

// ---------------- scratch (__device__ globals; no allocation) ---------------
__device__ float  g_S[(size_t)NB * SEQ * SEQ];            // fp32 scores
__device__ __half g_hh[NTOK * EMBED],  g_hl[NTOK * EMBED];
__device__ __half g_Wqh[KQD * EMBED],  g_Wql[KQD * EMBED];
__device__ __half g_Wkh[KQD * EMBED],  g_Wkl[KQD * EMBED];
__device__ __half g_Wvh[VDIM * EMBED], g_Wvl[VDIM * EMBED];
__device__ __half g_Qh[NTOK * KQD],  g_Ql[NTOK * KQD];
__device__ __half g_Kh[NTOK * KQD],  g_Kl[NTOK * KQD];
__device__ __half g_Vth[NB * VDIM * SEQ], g_Vtl[NB * VDIM * SEQ];  // V transposed
__device__ __half g_Atth[(size_t)NB * SEQ * SEQ], g_Attl[(size_t)NB * SEQ * SEQ];
__device__ __half g_Whh[(size_t)VOCAB * VDIM];
__device__ float  g_Cp[(size_t)NB * 4 * 72 * 128 * 128];  // ctx split-k partials
__device__ __half g_Ch[NTOK * VDIM];

// chunk-prefix table: S[m] = sum_{j<m} ceil((j+1)/2); S[16]=72
__device__ const int c_S[17] = {0,1,2,4,6,9,12,16,20,25,30,36,42,49,56,64,72};

struct HG {
    const __half* Ah[3]; const __half* Al[3];
    const __half* Bh[3]; const __half* Bl[3];
    float* C[3];
    __half* Oh[3]; __half* Ol[3];
};

// ---------------- helpers ----------------------------------------------------
__device__ __forceinline__ uint32_t s2u(const void* p) {
    uint32_t a;
    asm("{ .reg .u64 t; cvta.to.shared.u64 t, %1; cvt.u32.u64 %0, t; }"
        : "=r"(a) : "l"(p));
    return a;
}
__device__ __forceinline__ void cpa16(uint32_t d, const void* s) {
    asm volatile("cp.async.cg.shared.global [%0], [%1], 16;" :: "r"(d), "l"(s) : "memory");
}
__device__ __forceinline__ void cpcommit() {
    asm volatile("cp.async.commit_group;" ::: "memory");
}
template <int N> __device__ __forceinline__ void cpwait() {
    asm volatile("cp.async.wait_group %0;" :: "n"(N) : "memory");
}
__device__ __forceinline__ void mma_f16(float* acc, const uint32_t* a,
                                        const uint32_t* b) {
    asm("mma.sync.aligned.m16n8k16.row.col.f32.f16.f16.f32 "
        "{%0,%1,%2,%3}, {%4,%5,%6,%7}, {%8,%9}, {%0,%1,%2,%3};"
        : "+f"(acc[0]), "+f"(acc[1]), "+f"(acc[2]), "+f"(acc[3])
        : "r"(a[0]), "r"(a[1]), "r"(a[2]), "r"(a[3]), "r"(b[0]), "r"(b[1]));
}

// ---------------- stage 0: fp32 -> fp16 hi/lo split (weights) ---------------
__global__ void conv_split(const float* __restrict__ src, __half* __restrict__ dh,
                           __half* __restrict__ dl, int n) {
    int i = blockIdx.x * blockDim.x + threadIdx.x;
    const int stride = gridDim.x * blockDim.x;
    for (; i < n; i += stride) {
        float v = src[i];
        __half h = __float2half_rn(v);
        dh[i] = h;
        if (dl) dl[i] = __float2half_rn(v - __half2float(h));
    }
}

// ---------------- stage 1: h = emb[x] + PE -> fp16 hi/lo --------------------
__global__ void embed_pe_kernel(const int* __restrict__ x,
                                const float* __restrict__ emb) {
    int tok = blockIdx.x;
    int s = tok & (SEQ - 1);
    const float* e = emb + (size_t)x[tok] * EMBED;
    for (int i = threadIdx.x; i < EMBED; i += blockDim.x) {
        int j = i >> 1;
        float freq = expf((float)(2 * j) * (-9.210340371976184f / (float)EMBED));
        float ang = (float)s * freq;
        float pe = (i & 1) ? cosf(ang) : sinf(ang);
        float v = e[i] + pe;
        __half h = __float2half_rn(v);
        g_hh[tok * EMBED + i] = h;
        g_hl[tok * EMBED + i] = __float2half_rn(v - __half2float(h));
    }
}

// ---------------- unified NT fp16 tensor-core GEMM ---------------------------
// All operands pre-split fp16 hi/lo in global, NT layout (rows of length lda/ldb).
// NPASS=3: hi*hi + hi*lo + lo*hi; NPASS=1: hi*hi only.
// EPI=0: fp32 C (+bias,scale). EPI=1: QKV outputs (z<2 row hi/lo; z=2 V^T hi/lo).
// CHUNK: ctx split-k (blockIdx.x = chunk id, out -> Cp partial slot).
template <int NPASS, bool CAUSAL_OUT, bool BIAS, bool NXFAST, int EPI, bool CHUNK>
__global__ __launch_bounds__(256, 2)
void hgemm(HG g, const float* __restrict__ bias,
           int K, int lda, int ldb, int ldc, float scale,
           float* __restrict__ Cp) {
    int m0, n0, kbeg, kend;
    float* Cf = nullptr;
    const int z = blockIdx.z;
    if (CHUNK) {
        const int c = blockIdx.x;
        int m = 0;
#pragma unroll
        for (int j = 1; j <= 15; j++)
            if (c >= c_S[j]) m = j;
        const int kb = c - c_S[m];
        kbeg = kb * 256;
        kend = min((m + 1) * 128, kbeg + 256);
        m0 = m * 128;
        n0 = blockIdx.y * 128;
        Cf = Cp + (size_t)((z * 4 + blockIdx.y) * 72 + c) * 16384;
    } else {
        n0 = (NXFAST ? blockIdx.x : blockIdx.y) * 128;
        m0 = (NXFAST ? blockIdx.y : blockIdx.x) * 128;
        if (CAUSAL_OUT && n0 > m0 + 127) return;
        kbeg = 0; kend = K;
        if (EPI == 0) Cf = g.C[z];
    }
    const __half* gAh = g.Ah[z];
    const __half* gBh = g.Bh[z];

    __shared__ uint32_t Ash[2][128][12];
    __shared__ uint32_t Bsh[2][128][12];
    __shared__ uint32_t Asl[NPASS == 3 ? 2 : 1][NPASS == 3 ? 128 : 1][NPASS == 3 ? 12 : 1];
    __shared__ uint32_t Bsl[NPASS == 3 ? 2 : 1][NPASS == 3 ? 128 : 1][NPASS == 3 ? 12 : 1];

    const int tid = threadIdx.x, lane = tid & 31, wid = tid >> 5;
    const int warpM = wid >> 2, warpN = wid & 3, qr = lane >> 2, qc = lane & 3;
    const int frow = tid >> 1, fhalf = tid & 1;

    const uint32_t uAsh = s2u(Ash), uBsh = s2u(Bsh);
    const uint32_t uAsl = s2u(Asl), uBsl = s2u(Bsl);

    const __half* srcA = gAh + (size_t)(m0 + frow) * lda + kbeg + fhalf * 8;
    const __half* srcB = gBh + (size_t)(n0 + frow) * ldb + kbeg + fhalf * 8;
    const __half* srcAl = nullptr;
    const __half* srcBl = nullptr;
    if (NPASS == 3) {
        srcAl = g.Al[z] + (size_t)(m0 + frow) * lda + kbeg + fhalf * 8;
        srcBl = g.Bl[z] + (size_t)(n0 + frow) * ldb + kbeg + fhalf * 8;
    }
    const uint32_t doff = (uint32_t)(frow * 12 + fhalf * 4) * 4;

    auto fill = [&](int buf, int it) {
        const int ko = it * 16;
        const uint32_t db = (uint32_t)buf * 6144 + doff;
        cpa16(uAsh + db, srcA + ko);
        cpa16(uBsh + db, srcB + ko);
        if (NPASS == 3) {
            cpa16(uAsl + db, srcAl + ko);
            cpa16(uBsl + db, srcBl + ko);
        }
        cpcommit();
    };

    float acc[4][4][4] = {};
    const int NIT = (kend - kbeg) / 16;

    fill(0, 0);
    for (int it = 0; it < NIT; it++) {
        const int cur = it & 1;
        if (it + 1 < NIT) { fill(cur ^ 1, it + 1); cpwait<1>(); }
        else cpwait<0>();
        __syncthreads();

        uint32_t bh[4][2], bl[4][2];
#pragma unroll
        for (int nt = 0; nt < 4; nt++) {
            const int n = warpN * 32 + nt * 8 + qr;
            bh[nt][0] = Bsh[cur][n][qc];
            bh[nt][1] = Bsh[cur][n][qc + 4];
            if (NPASS == 3) {
                bl[nt][0] = Bsl[cur][n][qc];
                bl[nt][1] = Bsl[cur][n][qc + 4];
            }
        }
#pragma unroll
        for (int mt = 0; mt < 4; mt++) {
            const int r = warpM * 64 + mt * 16 + qr;
            uint32_t ah[4] = {Ash[cur][r][qc], Ash[cur][r + 8][qc],
                              Ash[cur][r][qc + 4], Ash[cur][r + 8][qc + 4]};
            uint32_t al[4];
            if (NPASS == 3) {
                al[0] = Asl[cur][r][qc];
                al[1] = Asl[cur][r + 8][qc];
                al[2] = Asl[cur][r][qc + 4];
                al[3] = Asl[cur][r + 8][qc + 4];
            }
#pragma unroll
            for (int nt = 0; nt < 4; nt++) {
                mma_f16(acc[mt][nt], ah, bh[nt]);
                if (NPASS == 3) {
                    mma_f16(acc[mt][nt], ah, bl[nt]);
                    mma_f16(acc[mt][nt], al, bh[nt]);
                }
            }
        }
        __syncthreads();
    }

    // ---- epilogue ----
    if (EPI == 0) {
        const int mo = CHUNK ? 0 : m0;
        const int no = CHUNK ? 0 : n0;
        const int ld = CHUNK ? 128 : ldc;
#pragma unroll
        for (int mt = 0; mt < 4; mt++) {
            const int r = mo + warpM * 64 + mt * 16 + qr;
#pragma unroll
            for (int nt = 0; nt < 4; nt++) {
                const int lc = warpN * 32 + nt * 8 + qc * 2;
                float2 bb = BIAS ? *(const float2*)&bias[n0 + lc]
                                 : make_float2(0.f, 0.f);
                float2 v0, v1;
                v0.x = acc[mt][nt][0] * scale + bb.x;
                v0.y = acc[mt][nt][1] * scale + bb.y;
                v1.x = acc[mt][nt][2] * scale + bb.x;
                v1.y = acc[mt][nt][3] * scale + bb.y;
                *(float2*)&Cf[(size_t)r * ld + no + lc] = v0;
                *(float2*)&Cf[(size_t)(r + 8) * ld + no + lc] = v1;
            }
        }
    } else {
        __half* oh = g.Oh[z];
        __half* ol = g.Ol[z];
#pragma unroll
        for (int mt = 0; mt < 4; mt++) {
            const int r = m0 + warpM * 64 + mt * 16 + qr;
#pragma unroll
            for (int nt = 0; nt < 4; nt++) {
                const int cc = n0 + warpN * 32 + nt * 8 + qc * 2;
                __half h[4], l[4];
#pragma unroll
                for (int j = 0; j < 4; j++) {
                    float v = acc[mt][nt][j];
                    h[j] = __float2half_rn(v);
                    l[j] = __float2half_rn(v - __half2float(h[j]));
                }
                if (z < 2) {
                    *(__half2*)&oh[(size_t)r * KQD + cc] = __halves2half2(h[0], h[1]);
                    *(__half2*)&oh[(size_t)(r + 8) * KQD + cc] = __halves2half2(h[2], h[3]);
                    *(__half2*)&ol[(size_t)r * KQD + cc] = __halves2half2(l[0], l[1]);
                    *(__half2*)&ol[(size_t)(r + 8) * KQD + cc] = __halves2half2(l[2], l[3]);
                } else {
#pragma unroll
                    for (int j = 0; j < 4; j++) {
                        const int rr = r + ((j >= 2) ? 8 : 0);
                        const int c = cc + (j & 1);
                        const int b = rr >> 11, s = rr & 2047;
                        const size_t o = ((size_t)b * VDIM + c) * SEQ + s;
                        oh[o] = h[j];
                        ol[o] = l[j];
                    }
                }
            }
        }
    }
}

// ---------------- stage 4: causal row softmax -> fp16 hi/lo attn ------------
__global__ void softmax_causal_kernel() {
    int row = blockIdx.x;
    int b = row / SEQ;
    int q = row & (SEQ - 1);
    const size_t boff = (size_t)b * SEQ * SEQ + (size_t)q * SEQ;
    float* r = g_S + boff;
    __half* oh = g_Atth + boff;
    __half* ol = g_Attl + boff;
    const int len = q + 1;

    __shared__ float redm[8];
    __shared__ float reds[8];
    __shared__ float bc[2];

    float m = -INFINITY;
    for (int i = threadIdx.x; i < len; i += 256) m = fmaxf(m, r[i]);
#pragma unroll
    for (int o = 16; o; o >>= 1) m = fmaxf(m, __shfl_xor_sync(0xffffffffu, m, o));
    if ((threadIdx.x & 31) == 0) redm[threadIdx.x >> 5] = m;
    __syncthreads();
    if (threadIdx.x == 0) {
        float v = redm[0];
#pragma unroll
        for (int w = 1; w < 8; w++) v = fmaxf(v, redm[w]);
        bc[0] = v;
    }
    __syncthreads();
    const float rmax = bc[0];

    float s = 0.f;
    for (int i = threadIdx.x; i < len; i += 256) {
        float e = __expf(r[i] - rmax);
        r[i] = e;
        s += e;
    }
#pragma unroll
    for (int o = 16; o; o >>= 1) s += __shfl_xor_sync(0xffffffffu, s, o);
    if ((threadIdx.x & 31) == 0) reds[threadIdx.x >> 5] = s;
    __syncthreads();
    if (threadIdx.x == 0) {
        float v = reds[0];
#pragma unroll
        for (int w = 1; w < 8; w++) v += reds[w];
        bc[1] = 1.0f / v;
    }
    __syncthreads();
    const float inv = bc[1];

    for (int i = threadIdx.x; i < len; i += 256) {
        float w = r[i] * inv;
        __half h = __float2half_rn(w);
        oh[i] = h;
        ol[i] = __float2half_rn(w - __half2float(h));
    }
    const __half z = __float2half_rn(0.f);
    for (int i = len + threadIdx.x; i < SEQ; i += 256) { oh[i] = z; ol[i] = z; }
}

// ---------------- ctx split-k reduce -> fp16 ctx ----------------------------
__global__ void reduce_ctx(const float* __restrict__ Cp, __half* __restrict__ Ch) {
    const int idx = blockIdx.x * 256 + threadIdx.x;   // 524288 total (float4 granular)
    const int tok = idx >> 7;
    const int v4 = idx & 127;
    const int b = tok >> 11, t = tok & 2047;
    const int m = t >> 7, row = t & 127;
    const int n = v4 >> 5, cc = (v4 & 31) * 4;
    const int s0 = c_S[m], cnt = (m + 2) >> 1;
    float4 a = make_float4(0.f, 0.f, 0.f, 0.f);
    for (int j = 0; j < cnt; j++) {
        const size_t slot = (size_t)((b * 4 + n) * 72 + s0 + j);
        const float4 p = *(const float4*)&Cp[slot * 16384 + row * 128 + cc];
        a.x += p.x; a.y += p.y; a.z += p.z; a.w += p.w;
    }
    const size_t o = (size_t)tok * VDIM + n * 128 + cc;
    *(__half2*)&g_Ch[o] = __halves2half2(__float2half_rn(a.x), __float2half_rn(a.y));
    *(__half2*)&g_Ch[o + 2] = __halves2half2(__float2half_rn(a.z), __float2half_rn(a.w));
    (void)Ch;
}

// ---------------- launch ----------------------------------------------------
extern "C" void kernel_launch(void* const* d_in, const int* in_sizes, int n_in,
                              void* d_out, int out_size) {
    const int*   x   = (const int*)d_in[0];
    const float* emb = (const float*)d_in[1];
    const float* Wq  = (const float*)d_in[2];
    const float* Wk  = (const float*)d_in[3];
    const float* Wv  = (const float*)d_in[4];
    const float* Wh  = (const float*)d_in[5];
    const float* bh  = (const float*)d_in[6];
    float* out = (float*)d_out;

    float *S, *Cp;
    cudaGetSymbolAddress((void**)&S, g_S);
    cudaGetSymbolAddress((void**)&Cp, g_Cp);
    __half *hh, *hl, *Wqh, *Wql, *Wkh, *Wkl, *Wvh, *Wvl;
    __half *Qh, *Ql, *Kh, *Kl, *Vth, *Vtl, *Ath, *Atl, *Whh, *Ch;
    cudaGetSymbolAddress((void**)&hh, g_hh);   cudaGetSymbolAddress((void**)&hl, g_hl);
    cudaGetSymbolAddress((void**)&Wqh, g_Wqh); cudaGetSymbolAddress((void**)&Wql, g_Wql);
    cudaGetSymbolAddress((void**)&Wkh, g_Wkh); cudaGetSymbolAddress((void**)&Wkl, g_Wkl);
    cudaGetSymbolAddress((void**)&Wvh, g_Wvh); cudaGetSymbolAddress((void**)&Wvl, g_Wvl);
    cudaGetSymbolAddress((void**)&Qh, g_Qh);   cudaGetSymbolAddress((void**)&Ql, g_Ql);
    cudaGetSymbolAddress((void**)&Kh, g_Kh);   cudaGetSymbolAddress((void**)&Kl, g_Kl);
    cudaGetSymbolAddress((void**)&Vth, g_Vth); cudaGetSymbolAddress((void**)&Vtl, g_Vtl);
    cudaGetSymbolAddress((void**)&Ath, g_Atth); cudaGetSymbolAddress((void**)&Atl, g_Attl);
    cudaGetSymbolAddress((void**)&Whh, g_Whh); cudaGetSymbolAddress((void**)&Ch, g_Ch);

    const float sscale = 22.627416997969522f;  // sqrt(512)
    const dim3 blk(256);

    // 0) weight splits
    conv_split<<<256, 256>>>(Wq, Wqh, Wql, KQD * EMBED);
    conv_split<<<256, 256>>>(Wk, Wkh, Wkl, KQD * EMBED);
    conv_split<<<256, 256>>>(Wv, Wvh, Wvl, VDIM * EMBED);
    conv_split<<<8192, 256>>>(Wh, Whh, nullptr, VOCAB * VDIM);

    // 1) embedding + PE -> hi/lo
    embed_pe_kernel<<<NTOK, 128>>>(x, emb);

    // 2) QKV (3-pass), epilogue emits Q/K row hi/lo + V^T hi/lo
    {
        HG g = {};
        g.Ah[0] = g.Ah[1] = g.Ah[2] = hh;
        g.Al[0] = g.Al[1] = g.Al[2] = hl;
        g.Bh[0] = Wqh; g.Bh[1] = Wkh; g.Bh[2] = Wvh;
        g.Bl[0] = Wql; g.Bl[1] = Wkl; g.Bl[2] = Wvl;
        g.Oh[0] = Qh; g.Oh[1] = Kh; g.Oh[2] = Vth;
        g.Ol[0] = Ql; g.Ol[1] = Kl; g.Ol[2] = Vtl;
        hgemm<3, false, false, true, 1, false><<<dim3(4, 32, 3), blk>>>(
            g, nullptr, EMBED, EMBED, EMBED, KQD, 1.f, nullptr);
    }

    // 3) scores = sqrt(512) * Q K^T (3-pass, causal tiles skipped)
    {
        HG g = {};
        for (int b = 0; b < NB; b++) {
            g.Ah[b] = Qh + (size_t)b * SEQ * KQD;
            g.Al[b] = Ql + (size_t)b * SEQ * KQD;
            g.Bh[b] = Kh + (size_t)b * SEQ * KQD;
            g.Bl[b] = Kl + (size_t)b * SEQ * KQD;
            g.C[b]  = S + (size_t)b * SEQ * SEQ;
        }
        hgemm<3, true, false, true, 0, false><<<dim3(16, 16, NB), blk>>>(
            g, nullptr, KQD, KQD, KQD, SEQ, sscale, nullptr);
    }

    // 4) softmax -> attn hi/lo fp16
    softmax_causal_kernel<<<NTOK, 256>>>();

    // 5) ctx = attn @ V^T, balanced 256-k chunks, split-k partials
    {
        HG g = {};
        for (int b = 0; b < NB; b++) {
            g.Ah[b] = Ath + (size_t)b * SEQ * SEQ;
            g.Al[b] = Atl + (size_t)b * SEQ * SEQ;
            g.Bh[b] = Vth + (size_t)b * VDIM * SEQ;
            g.Bl[b] = Vtl + (size_t)b * VDIM * SEQ;
        }
        hgemm<3, false, false, true, 0, true><<<dim3(72, 4, NB), blk>>>(
            g, nullptr, SEQ, SEQ, SEQ, 128, 1.f, Cp);
    }

    // 5b) reduce partials -> ctx fp16
    reduce_ctx<<<2048, 256>>>(Cp, Ch);

    // 6) logits = ctx @ Wh^T + bh (1-pass fp16; m tiles on fast axis for L2)
    {
        HG g = {};
        g.Ah[0] = Ch; g.Bh[0] = Whh; g.C[0] = out;
        hgemm<1, false, true, false, 0, false><<<dim3(32, 250, 1), blk>>>(
            g, bh, VDIM, VDIM, VDIM, VOCAB, 1.f, nullptr);
    }
}

// round 7
// speedup vs baseline: 1.8979x; 1.5643x over previous
#include <cuda_runtime.h>
#include <cuda_fp16.h>
#include <math.h>
#include <stdint.h>

#define VOCAB 32000
#define EMBED 512
#define KQD   512
#define VDIM  512
#define NB    2
#define SEQ   2048
#define NTOK  (NB * SEQ)

// ---------------- scratch (__device__ globals; no allocation) ---------------
__device__ float  g_S[(size_t)NB * SEQ * SEQ];            // fp32 scores
__device__ __half g_hh[NTOK * EMBED],  g_hl[NTOK * EMBED];
__device__ __half g_Wqh[KQD * EMBED],  g_Wql[KQD * EMBED];
__device__ __half g_Wkh[KQD * EMBED],  g_Wkl[KQD * EMBED];
__device__ __half g_Wvh[VDIM * EMBED], g_Wvl[VDIM * EMBED];
__device__ __half g_Qh[NTOK * KQD],  g_Ql[NTOK * KQD];
__device__ __half g_Kh[NTOK * KQD],  g_Kl[NTOK * KQD];
__device__ __half g_Vth[NB * VDIM * SEQ], g_Vtl[NB * VDIM * SEQ];  // V transposed
__device__ __half g_Atth[(size_t)NB * SEQ * SEQ], g_Attl[(size_t)NB * SEQ * SEQ];
__device__ __half g_Whh[(size_t)VOCAB * VDIM];
__device__ float  g_Cp[(size_t)NB * 4 * 72 * 128 * 128];  // ctx split-k partials
__device__ __half g_Ch[NTOK * VDIM];

// chunk-prefix table: S[m] = sum_{j<m} ceil((j+1)/2); S[16]=72
__device__ const int c_S[17] = {0,1,2,4,6,9,12,16,20,25,30,36,42,49,56,64,72};

struct HG {
    const __half* Ah[3]; const __half* Al[3];
    const __half* Bh[3]; const __half* Bl[3];
    float* C[3];
    __half* Oh[3]; __half* Ol[3];
};

// ---------------- helpers ----------------------------------------------------
__device__ __forceinline__ uint32_t s2u(const void* p) {
    uint32_t a;
    asm("{ .reg .u64 t; cvta.to.shared.u64 t, %1; cvt.u32.u64 %0, t; }"
        : "=r"(a) : "l"(p));
    return a;
}
__device__ __forceinline__ void cpa16(uint32_t d, const void* s) {
    asm volatile("cp.async.cg.shared.global [%0], [%1], 16;" :: "r"(d), "l"(s) : "memory");
}
__device__ __forceinline__ void cpcommit() {
    asm volatile("cp.async.commit_group;" ::: "memory");
}
template <int N> __device__ __forceinline__ void cpwait() {
    asm volatile("cp.async.wait_group %0;" :: "n"(N) : "memory");
}
__device__ __forceinline__ void mma_f16(float* acc, const uint32_t* a,
                                        const uint32_t* b) {
    asm("mma.sync.aligned.m16n8k16.row.col.f32.f16.f16.f32 "
        "{%0,%1,%2,%3}, {%4,%5,%6,%7}, {%8,%9}, {%0,%1,%2,%3};"
        : "+f"(acc[0]), "+f"(acc[1]), "+f"(acc[2]), "+f"(acc[3])
        : "r"(a[0]), "r"(a[1]), "r"(a[2]), "r"(a[3]), "r"(b[0]), "r"(b[1]));
}

// ---------------- stage 0: fp32 -> fp16 hi/lo split (vectorized) ------------
__global__ void conv_split(const float* __restrict__ src, __half* __restrict__ dh,
                           __half* __restrict__ dl, int n4) {
    const float4* s4 = (const float4*)src;
    int i = blockIdx.x * blockDim.x + threadIdx.x;
    const int stride = gridDim.x * blockDim.x;
    for (; i < n4; i += stride) {
        float4 v = s4[i];
        __half2 h0 = __floats2half2_rn(v.x, v.y);
        __half2 h1 = __floats2half2_rn(v.z, v.w);
        uint2 hp;
        hp.x = *(uint32_t*)&h0;
        hp.y = *(uint32_t*)&h1;
        *(uint2*)&dh[i * 4] = hp;
        if (dl) {
            __half2 l0 = __floats2half2_rn(v.x - __low2float(h0), v.y - __high2float(h0));
            __half2 l1 = __floats2half2_rn(v.z - __low2float(h1), v.w - __high2float(h1));
            uint2 lp;
            lp.x = *(uint32_t*)&l0;
            lp.y = *(uint32_t*)&l1;
            *(uint2*)&dl[i * 4] = lp;
        }
    }
}

// ---------------- stage 1: h = emb[x] + PE -> fp16 hi/lo --------------------
__global__ void embed_pe_kernel(const int* __restrict__ x,
                                const float* __restrict__ emb) {
    int tok = blockIdx.x;
    int s = tok & (SEQ - 1);
    const float* e = emb + (size_t)x[tok] * EMBED;
    for (int i = threadIdx.x; i < EMBED; i += blockDim.x) {
        int j = i >> 1;
        float freq = expf((float)(2 * j) * (-9.210340371976184f / (float)EMBED));
        float ang = (float)s * freq;
        float pe = (i & 1) ? cosf(ang) : sinf(ang);
        float v = e[i] + pe;
        __half h = __float2half_rn(v);
        g_hh[tok * EMBED + i] = h;
        g_hl[tok * EMBED + i] = __float2half_rn(v - __half2float(h));
    }
}

// ---------------- unified NT fp16 tensor-core GEMM ---------------------------
// All operands pre-split fp16 hi/lo in global, NT layout.
// NPASS=3: hi*hi + hi*lo + lo*hi; NPASS=1: hi*hi only.
// EPI=0: fp32 C (+bias,scale). EPI=1: QKV outputs (z<2 row hi/lo; z=2 V^T hi/lo).
// CHUNK: ctx split-k (blockIdx.x = chunk id, out -> Cp partial slot).
// Mainloop: single __syncthreads per 16-k iteration; cp.async prefetch issued
// right after the barrier so the next tile loads during the whole MMA phase.
template <int NPASS, bool CAUSAL_OUT, bool BIAS, bool NXFAST, int EPI, bool CHUNK>
__global__ __launch_bounds__(256, 2)
void hgemm(HG g, const float* __restrict__ bias,
           int K, int lda, int ldb, int ldc, float scale,
           float* __restrict__ Cp) {
    int m0, n0, kbeg, kend;
    float* Cf = nullptr;
    const int z = blockIdx.z;
    if (CHUNK) {
        const int c = blockIdx.x;
        int m = 0;
#pragma unroll
        for (int j = 1; j <= 15; j++)
            if (c >= c_S[j]) m = j;
        const int kb = c - c_S[m];
        kbeg = kb * 256;
        kend = min((m + 1) * 128, kbeg + 256);
        m0 = m * 128;
        n0 = blockIdx.y * 128;
        Cf = Cp + (size_t)((z * 4 + blockIdx.y) * 72 + c) * 16384;
    } else {
        n0 = (NXFAST ? blockIdx.x : blockIdx.y) * 128;
        m0 = (NXFAST ? blockIdx.y : blockIdx.x) * 128;
        if (CAUSAL_OUT && n0 > m0 + 127) return;
        kbeg = 0; kend = K;
        if (EPI == 0) Cf = g.C[z];
    }
    const __half* gAh = g.Ah[z];
    const __half* gBh = g.Bh[z];

    __shared__ uint32_t Ash[2][128][12];
    __shared__ uint32_t Bsh[2][128][12];
    __shared__ uint32_t Asl[NPASS == 3 ? 2 : 1][NPASS == 3 ? 128 : 1][NPASS == 3 ? 12 : 1];
    __shared__ uint32_t Bsl[NPASS == 3 ? 2 : 1][NPASS == 3 ? 128 : 1][NPASS == 3 ? 12 : 1];

    const int tid = threadIdx.x, lane = tid & 31, wid = tid >> 5;
    const int warpM = wid >> 2, warpN = wid & 3, qr = lane >> 2, qc = lane & 3;
    const int frow = tid >> 1, fhalf = tid & 1;

    const uint32_t uAsh = s2u(Ash), uBsh = s2u(Bsh);
    const uint32_t uAsl = s2u(Asl), uBsl = s2u(Bsl);

    const __half* srcA = gAh + (size_t)(m0 + frow) * lda + kbeg + fhalf * 8;
    const __half* srcB = gBh + (size_t)(n0 + frow) * ldb + kbeg + fhalf * 8;
    const __half* srcAl = nullptr;
    const __half* srcBl = nullptr;
    if (NPASS == 3) {
        srcAl = g.Al[z] + (size_t)(m0 + frow) * lda + kbeg + fhalf * 8;
        srcBl = g.Bl[z] + (size_t)(n0 + frow) * ldb + kbeg + fhalf * 8;
    }
    const uint32_t doff = (uint32_t)(frow * 12 + fhalf * 4) * 4;

    auto fill = [&](int buf, int it) {
        const int ko = it * 16;
        const uint32_t db = (uint32_t)buf * 6144 + doff;
        cpa16(uAsh + db, srcA + ko);
        cpa16(uBsh + db, srcB + ko);
        if (NPASS == 3) {
            cpa16(uAsl + db, srcAl + ko);
            cpa16(uBsl + db, srcBl + ko);
        }
        cpcommit();
    };

    float acc[4][4][4] = {};
    const int NIT = (kend - kbeg) / 16;

    fill(0, 0);
    for (int it = 0; it < NIT; it++) {
        const int cur = it & 1;
        cpwait<0>();
        __syncthreads();
        // prefetch next tile into other buffer; safe: all warps have finished
        // consuming it (barrier above covers compute of it-1), and it loads
        // during the whole MMA phase below.
        if (it + 1 < NIT) fill(cur ^ 1, it + 1);

        uint32_t bh[4][2], bl[4][2];
#pragma unroll
        for (int nt = 0; nt < 4; nt++) {
            const int n = warpN * 32 + nt * 8 + qr;
            bh[nt][0] = Bsh[cur][n][qc];
            bh[nt][1] = Bsh[cur][n][qc + 4];
            if (NPASS == 3) {
                bl[nt][0] = Bsl[cur][n][qc];
                bl[nt][1] = Bsl[cur][n][qc + 4];
            }
        }
#pragma unroll
        for (int mt = 0; mt < 4; mt++) {
            const int r = warpM * 64 + mt * 16 + qr;
            uint32_t ah[4] = {Ash[cur][r][qc], Ash[cur][r + 8][qc],
                              Ash[cur][r][qc + 4], Ash[cur][r + 8][qc + 4]};
            uint32_t al[4];
            if (NPASS == 3) {
                al[0] = Asl[cur][r][qc];
                al[1] = Asl[cur][r + 8][qc];
                al[2] = Asl[cur][r][qc + 4];
                al[3] = Asl[cur][r + 8][qc + 4];
            }
#pragma unroll
            for (int nt = 0; nt < 4; nt++) {
                mma_f16(acc[mt][nt], ah, bh[nt]);
                if (NPASS == 3) {
                    mma_f16(acc[mt][nt], ah, bl[nt]);
                    mma_f16(acc[mt][nt], al, bh[nt]);
                }
            }
        }
    }

    // ---- epilogue ----
    if (EPI == 0) {
        const int mo = CHUNK ? 0 : m0;
        const int no = CHUNK ? 0 : n0;
        const int ld = CHUNK ? 128 : ldc;
#pragma unroll
        for (int mt = 0; mt < 4; mt++) {
            const int r = mo + warpM * 64 + mt * 16 + qr;
#pragma unroll
            for (int nt = 0; nt < 4; nt++) {
                const int lc = warpN * 32 + nt * 8 + qc * 2;
                float2 bb = BIAS ? *(const float2*)&bias[n0 + lc]
                                 : make_float2(0.f, 0.f);
                float2 v0, v1;
                v0.x = acc[mt][nt][0] * scale + bb.x;
                v0.y = acc[mt][nt][1] * scale + bb.y;
                v1.x = acc[mt][nt][2] * scale + bb.x;
                v1.y = acc[mt][nt][3] * scale + bb.y;
                *(float2*)&Cf[(size_t)r * ld + no + lc] = v0;
                *(float2*)&Cf[(size_t)(r + 8) * ld + no + lc] = v1;
            }
        }
    } else {
        __half* oh = g.Oh[z];
        __half* ol = g.Ol[z];
#pragma unroll
        for (int mt = 0; mt < 4; mt++) {
            const int r = m0 + warpM * 64 + mt * 16 + qr;
#pragma unroll
            for (int nt = 0; nt < 4; nt++) {
                const int cc = n0 + warpN * 32 + nt * 8 + qc * 2;
                __half h[4], l[4];
#pragma unroll
                for (int j = 0; j < 4; j++) {
                    float v = acc[mt][nt][j];
                    h[j] = __float2half_rn(v);
                    l[j] = __float2half_rn(v - __half2float(h[j]));
                }
                if (z < 2) {
                    *(__half2*)&oh[(size_t)r * KQD + cc] = __halves2half2(h[0], h[1]);
                    *(__half2*)&oh[(size_t)(r + 8) * KQD + cc] = __halves2half2(h[2], h[3]);
                    *(__half2*)&ol[(size_t)r * KQD + cc] = __halves2half2(l[0], l[1]);
                    *(__half2*)&ol[(size_t)(r + 8) * KQD + cc] = __halves2half2(l[2], l[3]);
                } else {
#pragma unroll
                    for (int j = 0; j < 4; j++) {
                        const int rr = r + ((j >= 2) ? 8 : 0);
                        const int c = cc + (j & 1);
                        const int b = rr >> 11, s = rr & 2047;
                        const size_t o = ((size_t)b * VDIM + c) * SEQ + s;
                        oh[o] = h[j];
                        ol[o] = l[j];
                    }
                }
            }
        }
    }
}

// ---------------- stage 4: causal row softmax -> fp16 hi/lo attn ------------
__global__ void softmax_causal_kernel() {
    int row = blockIdx.x;
    int b = row / SEQ;
    int q = row & (SEQ - 1);
    const size_t boff = (size_t)b * SEQ * SEQ + (size_t)q * SEQ;
    float* r = g_S + boff;
    __half* oh = g_Atth + boff;
    __half* ol = g_Attl + boff;
    const int len = q + 1;

    __shared__ float redm[8];
    __shared__ float reds[8];
    __shared__ float bc[2];

    float m = -INFINITY;
    for (int i = threadIdx.x; i < len; i += 256) m = fmaxf(m, r[i]);
#pragma unroll
    for (int o = 16; o; o >>= 1) m = fmaxf(m, __shfl_xor_sync(0xffffffffu, m, o));
    if ((threadIdx.x & 31) == 0) redm[threadIdx.x >> 5] = m;
    __syncthreads();
    if (threadIdx.x == 0) {
        float v = redm[0];
#pragma unroll
        for (int w = 1; w < 8; w++) v = fmaxf(v, redm[w]);
        bc[0] = v;
    }
    __syncthreads();
    const float rmax = bc[0];

    float s = 0.f;
    for (int i = threadIdx.x; i < len; i += 256) {
        float e = __expf(r[i] - rmax);
        r[i] = e;
        s += e;
    }
#pragma unroll
    for (int o = 16; o; o >>= 1) s += __shfl_xor_sync(0xffffffffu, s, o);
    if ((threadIdx.x & 31) == 0) reds[threadIdx.x >> 5] = s;
    __syncthreads();
    if (threadIdx.x == 0) {
        float v = reds[0];
#pragma unroll
        for (int w = 1; w < 8; w++) v += reds[w];
        bc[1] = 1.0f / v;
    }
    __syncthreads();
    const float inv = bc[1];

    for (int i = threadIdx.x; i < len; i += 256) {
        float w = r[i] * inv;
        __half h = __float2half_rn(w);
        oh[i] = h;
        ol[i] = __float2half_rn(w - __half2float(h));
    }
    const __half zz = __float2half_rn(0.f);
    for (int i = len + threadIdx.x; i < SEQ; i += 256) { oh[i] = zz; ol[i] = zz; }
}

// ---------------- ctx split-k reduce -> fp16 ctx ----------------------------
__global__ void reduce_ctx(const float* __restrict__ Cp, __half* __restrict__ Ch) {
    const int idx = blockIdx.x * 256 + threadIdx.x;   // 524288 total (float4 granular)
    const int tok = idx >> 7;
    const int v4 = idx & 127;
    const int b = tok >> 11, t = tok & 2047;
    const int m = t >> 7, row = t & 127;
    const int n = v4 >> 5, cc = (v4 & 31) * 4;
    const int s0 = c_S[m], cnt = (m + 2) >> 1;
    float4 a = make_float4(0.f, 0.f, 0.f, 0.f);
    for (int j = 0; j < cnt; j++) {
        const size_t slot = (size_t)((b * 4 + n) * 72 + s0 + j);
        const float4 p = *(const float4*)&Cp[slot * 16384 + row * 128 + cc];
        a.x += p.x; a.y += p.y; a.z += p.z; a.w += p.w;
    }
    const size_t o = (size_t)tok * VDIM + n * 128 + cc;
    *(__half2*)&g_Ch[o] = __halves2half2(__float2half_rn(a.x), __float2half_rn(a.y));
    *(__half2*)&g_Ch[o + 2] = __halves2half2(__float2half_rn(a.z), __float2half_rn(a.w));
    (void)Ch;
}

// ---------------- launch ----------------------------------------------------
extern "C" void kernel_launch(void* const* d_in, const int* in_sizes, int n_in,
                              void* d_out, int out_size) {
    const int*   x   = (const int*)d_in[0];
    const float* emb = (const float*)d_in[1];
    const float* Wq  = (const float*)d_in[2];
    const float* Wk  = (const float*)d_in[3];
    const float* Wv  = (const float*)d_in[4];
    const float* Wh  = (const float*)d_in[5];
    const float* bh  = (const float*)d_in[6];
    float* out = (float*)d_out;

    float *S, *Cp;
    cudaGetSymbolAddress((void**)&S, g_S);
    cudaGetSymbolAddress((void**)&Cp, g_Cp);
    __half *hh, *hl, *Wqh, *Wql, *Wkh, *Wkl, *Wvh, *Wvl;
    __half *Qh, *Ql, *Kh, *Kl, *Vth, *Vtl, *Ath, *Atl, *Whh, *Ch;
    cudaGetSymbolAddress((void**)&hh, g_hh);   cudaGetSymbolAddress((void**)&hl, g_hl);
    cudaGetSymbolAddress((void**)&Wqh, g_Wqh); cudaGetSymbolAddress((void**)&Wql, g_Wql);
    cudaGetSymbolAddress((void**)&Wkh, g_Wkh); cudaGetSymbolAddress((void**)&Wkl, g_Wkl);
    cudaGetSymbolAddress((void**)&Wvh, g_Wvh); cudaGetSymbolAddress((void**)&Wvl, g_Wvl);
    cudaGetSymbolAddress((void**)&Qh, g_Qh);   cudaGetSymbolAddress((void**)&Ql, g_Ql);
    cudaGetSymbolAddress((void**)&Kh, g_Kh);   cudaGetSymbolAddress((void**)&Kl, g_Kl);
    cudaGetSymbolAddress((void**)&Vth, g_Vth); cudaGetSymbolAddress((void**)&Vtl, g_Vtl);
    cudaGetSymbolAddress((void**)&Ath, g_Atth); cudaGetSymbolAddress((void**)&Atl, g_Attl);
    cudaGetSymbolAddress((void**)&Whh, g_Whh); cudaGetSymbolAddress((void**)&Ch, g_Ch);

    const float sscale = 22.627416997969522f;  // sqrt(512)
    const dim3 blk(256);

    // 0) weight splits (vectorized; n passed as count of float4s)
    conv_split<<<256, 256>>>(Wq, Wqh, Wql, KQD * EMBED / 4);
    conv_split<<<256, 256>>>(Wk, Wkh, Wkl, KQD * EMBED / 4);
    conv_split<<<256, 256>>>(Wv, Wvh, Wvl, VDIM * EMBED / 4);
    conv_split<<<4096, 256>>>(Wh, Whh, nullptr, VOCAB * VDIM / 4);

    // 1) embedding + PE -> hi/lo
    embed_pe_kernel<<<NTOK, 128>>>(x, emb);

    // 2) QKV (3-pass), epilogue emits Q/K row hi/lo + V^T hi/lo
    {
        HG g = {};
        g.Ah[0] = g.Ah[1] = g.Ah[2] = hh;
        g.Al[0] = g.Al[1] = g.Al[2] = hl;
        g.Bh[0] = Wqh; g.Bh[1] = Wkh; g.Bh[2] = Wvh;
        g.Bl[0] = Wql; g.Bl[1] = Wkl; g.Bl[2] = Wvl;
        g.Oh[0] = Qh; g.Oh[1] = Kh; g.Oh[2] = Vth;
        g.Ol[0] = Ql; g.Ol[1] = Kl; g.Ol[2] = Vtl;
        hgemm<3, false, false, true, 1, false><<<dim3(4, 32, 3), blk>>>(
            g, nullptr, EMBED, EMBED, EMBED, KQD, 1.f, nullptr);
    }

    // 3) scores = sqrt(512) * Q K^T (3-pass, causal tiles skipped)
    {
        HG g = {};
        for (int b = 0; b < NB; b++) {
            g.Ah[b] = Qh + (size_t)b * SEQ * KQD;
            g.Al[b] = Ql + (size_t)b * SEQ * KQD;
            g.Bh[b] = Kh + (size_t)b * SEQ * KQD;
            g.Bl[b] = Kl + (size_t)b * SEQ * KQD;
            g.C[b]  = S + (size_t)b * SEQ * SEQ;
        }
        hgemm<3, true, false, true, 0, false><<<dim3(16, 16, NB), blk>>>(
            g, nullptr, KQD, KQD, KQD, SEQ, sscale, nullptr);
    }

    // 4) softmax -> attn hi/lo fp16
    softmax_causal_kernel<<<NTOK, 256>>>();

    // 5) ctx = attn @ V^T, balanced 256-k chunks, split-k partials
    {
        HG g = {};
        for (int b = 0; b < NB; b++) {
            g.Ah[b] = Ath + (size_t)b * SEQ * SEQ;
            g.Al[b] = Atl + (size_t)b * SEQ * SEQ;
            g.Bh[b] = Vth + (size_t)b * VDIM * SEQ;
            g.Bl[b] = Vtl + (size_t)b * VDIM * SEQ;
        }
        hgemm<3, false, false, true, 0, true><<<dim3(72, 4, NB), blk>>>(
            g, nullptr, SEQ, SEQ, SEQ, 128, 1.f, Cp);
    }

    // 5b) reduce partials -> ctx fp16
    reduce_ctx<<<2048, 256>>>(Cp, Ch);

    // 6) logits = ctx @ Wh^T + bh (1-pass fp16; m tiles on fast axis for L2)
    {
        HG g = {};
        g.Ah[0] = Ch; g.Bh[0] = Whh; g.C[0] = out;
        hgemm<1, false, true, false, 0, false><<<dim3(32, 250, 1), blk>>>(
            g, bh, VDIM, VDIM, VDIM, VOCAB, 1.f, nullptr);
    }
}

// round 11
// speedup vs baseline: 2.1860x; 1.1518x over previous
#include <cuda_runtime.h>
#include <cuda_fp16.h>
#include <math.h>
#include <stdint.h>

#define VOCAB 32000
#define EMBED 512
#define KQD   512
#define VDIM  512
#define NB    2
#define SEQ   2048
#define NTOK  (NB * SEQ)

// ---------------- scratch (__device__ globals; no allocation) ---------------
__device__ float  g_S[(size_t)NB * SEQ * SEQ];            // fp32 scores
__device__ __half g_hh[NTOK * EMBED],  g_hl[NTOK * EMBED];
__device__ __half g_Wqh[KQD * EMBED],  g_Wql[KQD * EMBED];
__device__ __half g_Wkh[KQD * EMBED],  g_Wkl[KQD * EMBED];
__device__ __half g_Wvh[VDIM * EMBED], g_Wvl[VDIM * EMBED];
__device__ __half g_Qh[NTOK * KQD],  g_Ql[NTOK * KQD];
__device__ __half g_Kh[NTOK * KQD],  g_Kl[NTOK * KQD];
__device__ __half g_Vth[NB * VDIM * SEQ], g_Vtl[NB * VDIM * SEQ];  // V transposed
__device__ __half g_Atth[(size_t)NB * SEQ * SEQ], g_Attl[(size_t)NB * SEQ * SEQ];
__device__ __half g_Whh[(size_t)VOCAB * VDIM];
__device__ float  g_Cp[(size_t)NB * 4 * 72 * 128 * 128];  // ctx split-k partials
__device__ __half g_Ch[NTOK * VDIM];

// chunk-prefix table: S[m] = sum_{j<m} ceil((j+1)/2); S[16]=72
__device__ const int c_S[17] = {0,1,2,4,6,9,12,16,20,25,30,36,42,49,56,64,72};

struct HG {
    const __half* Ah[3]; const __half* Al[3];
    const __half* Bh[3]; const __half* Bl[3];
    float* C[3];
    __half* Oh[3]; __half* Ol[3];
};

// ---------------- helpers ----------------------------------------------------
__device__ __forceinline__ uint32_t s2u(const void* p) {
    uint32_t a;
    asm("{ .reg .u64 t; cvta.to.shared.u64 t, %1; cvt.u32.u64 %0, t; }"
        : "=r"(a) : "l"(p));
    return a;
}
__device__ __forceinline__ void cpa16(uint32_t d, const void* s) {
    asm volatile("cp.async.cg.shared.global [%0], [%1], 16;" :: "r"(d), "l"(s) : "memory");
}
__device__ __forceinline__ void cpcommit() {
    asm volatile("cp.async.commit_group;" ::: "memory");
}
template <int N> __device__ __forceinline__ void cpwait() {
    asm volatile("cp.async.wait_group %0;" :: "n"(N) : "memory");
}
__device__ __forceinline__ void mma_f16(float* acc, const uint32_t* a,
                                        const uint32_t* b) {
    asm("mma.sync.aligned.m16n8k16.row.col.f32.f16.f16.f32 "
        "{%0,%1,%2,%3}, {%4,%5,%6,%7}, {%8,%9}, {%0,%1,%2,%3};"
        : "+f"(acc[0]), "+f"(acc[1]), "+f"(acc[2]), "+f"(acc[3])
        : "r"(a[0]), "r"(a[1]), "r"(a[2]), "r"(a[3]), "r"(b[0]), "r"(b[1]));
}

// ---------------- stage 0: fp32 -> fp16 hi/lo split (vectorized) ------------
__global__ void conv_split(const float* __restrict__ src, __half* __restrict__ dh,
                           __half* __restrict__ dl, int n4) {
    const float4* s4 = (const float4*)src;
    int i = blockIdx.x * blockDim.x + threadIdx.x;
    const int stride = gridDim.x * blockDim.x;
    for (; i < n4; i += stride) {
        float4 v = s4[i];
        __half2 h0 = __floats2half2_rn(v.x, v.y);
        __half2 h1 = __floats2half2_rn(v.z, v.w);
        uint2 hp;
        hp.x = *(uint32_t*)&h0;
        hp.y = *(uint32_t*)&h1;
        *(uint2*)&dh[i * 4] = hp;
        if (dl) {
            __half2 l0 = __floats2half2_rn(v.x - __low2float(h0), v.y - __high2float(h0));
            __half2 l1 = __floats2half2_rn(v.z - __low2float(h1), v.w - __high2float(h1));
            uint2 lp;
            lp.x = *(uint32_t*)&l0;
            lp.y = *(uint32_t*)&l1;
            *(uint2*)&dl[i * 4] = lp;
        }
    }
}

// ---------------- stage 1: h = emb[x] + PE -> fp16 hi/lo --------------------
__global__ void embed_pe_kernel(const int* __restrict__ x,
                                const float* __restrict__ emb) {
    int tok = blockIdx.x;
    int s = tok & (SEQ - 1);
    const float* e = emb + (size_t)x[tok] * EMBED;
    for (int i = threadIdx.x; i < EMBED; i += blockDim.x) {
        int j = i >> 1;
        float freq = expf((float)(2 * j) * (-9.210340371976184f / (float)EMBED));
        float ang = (float)s * freq;
        float pe = (i & 1) ? cosf(ang) : sinf(ang);
        float v = e[i] + pe;
        __half h = __float2half_rn(v);
        g_hh[tok * EMBED + i] = h;
        g_hl[tok * EMBED + i] = __float2half_rn(v - __half2float(h));
    }
}

// ---------------- unified NT fp16 tensor-core GEMM ---------------------------
// All operands pre-split fp16 hi/lo in global, NT layout.
// NPASS=3: hi*hi + hi*lo + lo*hi; NPASS=1: hi*hi only.
// KTILE: k per pipeline stage (16 for 3-pass, 32 for 1-pass logits).
// Depth-3 cp.async pipeline, ONE __syncthreads per stage; prefetch is issued
// 2 stages ahead so each load gets two full compute phases to land.
template <int NPASS, int KTILE, bool CAUSAL_OUT, bool BIAS, bool NXFAST, int EPI, bool CHUNK>
__global__ __launch_bounds__(256, 2)
void hgemm(HG g, const float* __restrict__ bias,
           int K, int lda, int ldb, int ldc, float scale,
           float* __restrict__ Cp) {
    constexpr int KW = KTILE / 2;            // uint32 words per row per stage
    constexpr int PW = KW + 4;               // padded row (conflict-free frags)
    constexpr int ARRS = (NPASS == 3) ? 4 : 2;
    constexpr int ABUF = 128 * PW;           // words per array per buffer
    constexpr int BUFW = ARRS * ABUF;        // words per buffer
    constexpr int CPR = KW / 4;              // 16B chunks per row
    constexpr int CPT = (128 * CPR) / 256;   // chunks per thread per array

    extern __shared__ uint32_t sm[];

    int m0, n0, kbeg, kend;
    float* Cf = nullptr;
    const int z = blockIdx.z;
    if (CHUNK) {
        const int c = blockIdx.x;
        int m = 0;
#pragma unroll
        for (int j = 1; j <= 15; j++)
            if (c >= c_S[j]) m = j;
        const int kb = c - c_S[m];
        kbeg = kb * 256;
        kend = min((m + 1) * 128, kbeg + 256);
        m0 = m * 128;
        n0 = blockIdx.y * 128;
        Cf = Cp + (size_t)((z * 4 + blockIdx.y) * 72 + c) * 16384;
    } else {
        n0 = (NXFAST ? blockIdx.x : blockIdx.y) * 128;
        m0 = (NXFAST ? blockIdx.y : blockIdx.x) * 128;
        if (CAUSAL_OUT && n0 > m0 + 127) return;
        kbeg = 0; kend = K;
        if (EPI == 0) Cf = g.C[z];
    }
    const __half* gAh = g.Ah[z];
    const __half* gBh = g.Bh[z];
    const __half* gAl = (NPASS == 3) ? g.Al[z] : nullptr;
    const __half* gBl = (NPASS == 3) ? g.Bl[z] : nullptr;

    const int tid = threadIdx.x, lane = tid & 31, wid = tid >> 5;
    const int warpM = wid >> 2, warpN = wid & 3, qr = lane >> 2, qc = lane & 3;
    const uint32_t usm = s2u(sm);

    auto fill = [&](int buf, int it) {
        const int ko = kbeg + it * KTILE;
#pragma unroll
        for (int j = 0; j < CPT; j++) {
            const int c = tid + j * 256;
            const int row = c / CPR, kc = c % CPR;
            const uint32_t d = usm + 4u * ((uint32_t)buf * BUFW + row * PW + kc * 4);
            cpa16(d, gAh + (size_t)(m0 + row) * lda + ko + kc * 8);
            cpa16(d + 4u * ABUF, gBh + (size_t)(n0 + row) * ldb + ko + kc * 8);
            if (NPASS == 3) {
                cpa16(d + 8u * ABUF, gAl + (size_t)(m0 + row) * lda + ko + kc * 8);
                cpa16(d + 12u * ABUF, gBl + (size_t)(n0 + row) * ldb + ko + kc * 8);
            }
        }
        cpcommit();
    };

    float acc[4][4][4] = {};
    const int NIT = (kend - kbeg) / KTILE;

    fill(0, 0);
    if (NIT > 1) fill(1, 1);
    for (int it = 0; it < NIT; it++) {
        const int cur = it % 3;
        if (it + 1 < NIT) cpwait<1>();   // buffer `it` complete (newest is it+1)
        else cpwait<0>();
        __syncthreads();
        if (it + 2 < NIT) fill((it + 2) % 3, it + 2);  // overwrites buf of it-1: safe post-barrier

        const uint32_t* Ab  = sm + cur * BUFW;
        const uint32_t* Bb  = Ab + ABUF;
        const uint32_t* Alb = Ab + 2 * ABUF;
        const uint32_t* Blb = Ab + 3 * ABUF;

#pragma unroll
        for (int ks = 0; ks < KTILE / 16; ks++) {
            const int kb = ks * 8;
            uint32_t bh[4][2], bl[4][2];
#pragma unroll
            for (int nt = 0; nt < 4; nt++) {
                const int n = warpN * 32 + nt * 8 + qr;
                bh[nt][0] = Bb[n * PW + kb + qc];
                bh[nt][1] = Bb[n * PW + kb + qc + 4];
                if (NPASS == 3) {
                    bl[nt][0] = Blb[n * PW + kb + qc];
                    bl[nt][1] = Blb[n * PW + kb + qc + 4];
                }
            }
#pragma unroll
            for (int mt = 0; mt < 4; mt++) {
                const int r = warpM * 64 + mt * 16 + qr;
                uint32_t ah[4] = {Ab[r * PW + kb + qc], Ab[(r + 8) * PW + kb + qc],
                                  Ab[r * PW + kb + qc + 4], Ab[(r + 8) * PW + kb + qc + 4]};
                uint32_t al[4];
                if (NPASS == 3) {
                    al[0] = Alb[r * PW + kb + qc];
                    al[1] = Alb[(r + 8) * PW + kb + qc];
                    al[2] = Alb[r * PW + kb + qc + 4];
                    al[3] = Alb[(r + 8) * PW + kb + qc + 4];
                }
#pragma unroll
                for (int nt = 0; nt < 4; nt++) {
                    mma_f16(acc[mt][nt], ah, bh[nt]);
                    if (NPASS == 3) {
                        mma_f16(acc[mt][nt], ah, bl[nt]);
                        mma_f16(acc[mt][nt], al, bh[nt]);
                    }
                }
            }
        }
    }

    // ---- epilogue ----
    if (EPI == 0) {
        const int mo = CHUNK ? 0 : m0;
        const int no = CHUNK ? 0 : n0;
        const int ld = CHUNK ? 128 : ldc;
#pragma unroll
        for (int mt = 0; mt < 4; mt++) {
            const int r = mo + warpM * 64 + mt * 16 + qr;
#pragma unroll
            for (int nt = 0; nt < 4; nt++) {
                const int lc = warpN * 32 + nt * 8 + qc * 2;
                float2 bb = BIAS ? *(const float2*)&bias[n0 + lc]
                                 : make_float2(0.f, 0.f);
                float2 v0, v1;
                v0.x = acc[mt][nt][0] * scale + bb.x;
                v0.y = acc[mt][nt][1] * scale + bb.y;
                v1.x = acc[mt][nt][2] * scale + bb.x;
                v1.y = acc[mt][nt][3] * scale + bb.y;
                *(float2*)&Cf[(size_t)r * ld + no + lc] = v0;
                *(float2*)&Cf[(size_t)(r + 8) * ld + no + lc] = v1;
            }
        }
    } else {
        __half* oh = g.Oh[z];
        __half* ol = g.Ol[z];
#pragma unroll
        for (int mt = 0; mt < 4; mt++) {
            const int r = m0 + warpM * 64 + mt * 16 + qr;
#pragma unroll
            for (int nt = 0; nt < 4; nt++) {
                const int cc = n0 + warpN * 32 + nt * 8 + qc * 2;
                __half h[4], l[4];
#pragma unroll
                for (int j = 0; j < 4; j++) {
                    float v = acc[mt][nt][j];
                    h[j] = __float2half_rn(v);
                    l[j] = __float2half_rn(v - __half2float(h[j]));
                }
                if (z < 2) {
                    *(__half2*)&oh[(size_t)r * KQD + cc] = __halves2half2(h[0], h[1]);
                    *(__half2*)&oh[(size_t)(r + 8) * KQD + cc] = __halves2half2(h[2], h[3]);
                    *(__half2*)&ol[(size_t)r * KQD + cc] = __halves2half2(l[0], l[1]);
                    *(__half2*)&ol[(size_t)(r + 8) * KQD + cc] = __halves2half2(l[2], l[3]);
                } else {
#pragma unroll
                    for (int j = 0; j < 4; j++) {
                        const int rr = r + ((j >= 2) ? 8 : 0);
                        const int c = cc + (j & 1);
                        const int b = rr >> 11, s = rr & 2047;
                        const size_t o = ((size_t)b * VDIM + c) * SEQ + s;
                        oh[o] = h[j];
                        ol[o] = l[j];
                    }
                }
            }
        }
    }
}

// ---------------- stage 4: causal row softmax -> fp16 hi/lo attn ------------
__global__ void softmax_causal_kernel() {
    int row = blockIdx.x;
    int b = row / SEQ;
    int q = row & (SEQ - 1);
    const size_t boff = (size_t)b * SEQ * SEQ + (size_t)q * SEQ;
    float* r = g_S + boff;
    __half* oh = g_Atth + boff;
    __half* ol = g_Attl + boff;
    const int len = q + 1;

    __shared__ float redm[8];
    __shared__ float reds[8];
    __shared__ float bc[2];

    float m = -INFINITY;
    for (int i = threadIdx.x; i < len; i += 256) m = fmaxf(m, r[i]);
#pragma unroll
    for (int o = 16; o; o >>= 1) m = fmaxf(m, __shfl_xor_sync(0xffffffffu, m, o));
    if ((threadIdx.x & 31) == 0) redm[threadIdx.x >> 5] = m;
    __syncthreads();
    if (threadIdx.x == 0) {
        float v = redm[0];
#pragma unroll
        for (int w = 1; w < 8; w++) v = fmaxf(v, redm[w]);
        bc[0] = v;
    }
    __syncthreads();
    const float rmax = bc[0];

    float s = 0.f;
    for (int i = threadIdx.x; i < len; i += 256) {
        float e = __expf(r[i] - rmax);
        r[i] = e;
        s += e;
    }
#pragma unroll
    for (int o = 16; o; o >>= 1) s += __shfl_xor_sync(0xffffffffu, s, o);
    if ((threadIdx.x & 31) == 0) reds[threadIdx.x >> 5] = s;
    __syncthreads();
    if (threadIdx.x == 0) {
        float v = reds[0];
#pragma unroll
        for (int w = 1; w < 8; w++) v += reds[w];
        bc[1] = 1.0f / v;
    }
    __syncthreads();
    const float inv = bc[1];

    for (int i = threadIdx.x; i < len; i += 256) {
        float w = r[i] * inv;
        __half h = __float2half_rn(w);
        oh[i] = h;
        ol[i] = __float2half_rn(w - __half2float(h));
    }
    const __half zz = __float2half_rn(0.f);
    for (int i = len + threadIdx.x; i < SEQ; i += 256) { oh[i] = zz; ol[i] = zz; }
}

// ---------------- ctx split-k reduce -> fp16 ctx ----------------------------
__global__ void reduce_ctx(const float* __restrict__ Cp, __half* __restrict__ Ch) {
    const int idx = blockIdx.x * 256 + threadIdx.x;
    const int tok = idx >> 7;
    const int v4 = idx & 127;
    const int b = tok >> 11, t = tok & 2047;
    const int m = t >> 7, row = t & 127;
    const int n = v4 >> 5, cc = (v4 & 31) * 4;
    const int s0 = c_S[m], cnt = (m + 2) >> 1;
    float4 a = make_float4(0.f, 0.f, 0.f, 0.f);
    for (int j = 0; j < cnt; j++) {
        const size_t slot = (size_t)((b * 4 + n) * 72 + s0 + j);
        const float4 p = *(const float4*)&Cp[slot * 16384 + row * 128 + cc];
        a.x += p.x; a.y += p.y; a.z += p.z; a.w += p.w;
    }
    const size_t o = (size_t)tok * VDIM + n * 128 + cc;
    *(__half2*)&g_Ch[o] = __halves2half2(__float2half_rn(a.x), __float2half_rn(a.y));
    *(__half2*)&g_Ch[o + 2] = __halves2half2(__float2half_rn(a.z), __float2half_rn(a.w));
    (void)Ch;
}

// ---------------- launch ----------------------------------------------------
extern "C" void kernel_launch(void* const* d_in, const int* in_sizes, int n_in,
                              void* d_out, int out_size) {
    const int*   x   = (const int*)d_in[0];
    const float* emb = (const float*)d_in[1];
    const float* Wq  = (const float*)d_in[2];
    const float* Wk  = (const float*)d_in[3];
    const float* Wv  = (const float*)d_in[4];
    const float* Wh  = (const float*)d_in[5];
    const float* bh  = (const float*)d_in[6];
    float* out = (float*)d_out;

    float *S, *Cp;
    cudaGetSymbolAddress((void**)&S, g_S);
    cudaGetSymbolAddress((void**)&Cp, g_Cp);
    __half *hh, *hl, *Wqh, *Wql, *Wkh, *Wkl, *Wvh, *Wvl;
    __half *Qh, *Ql, *Kh, *Kl, *Vth, *Vtl, *Ath, *Atl, *Whh, *Ch;
    cudaGetSymbolAddress((void**)&hh, g_hh);   cudaGetSymbolAddress((void**)&hl, g_hl);
    cudaGetSymbolAddress((void**)&Wqh, g_Wqh); cudaGetSymbolAddress((void**)&Wql, g_Wql);
    cudaGetSymbolAddress((void**)&Wkh, g_Wkh); cudaGetSymbolAddress((void**)&Wkl, g_Wkl);
    cudaGetSymbolAddress((void**)&Wvh, g_Wvh); cudaGetSymbolAddress((void**)&Wvl, g_Wvl);
    cudaGetSymbolAddress((void**)&Qh, g_Qh);   cudaGetSymbolAddress((void**)&Ql, g_Ql);
    cudaGetSymbolAddress((void**)&Kh, g_Kh);   cudaGetSymbolAddress((void**)&Kl, g_Kl);
    cudaGetSymbolAddress((void**)&Vth, g_Vth); cudaGetSymbolAddress((void**)&Vtl, g_Vtl);
    cudaGetSymbolAddress((void**)&Ath, g_Atth); cudaGetSymbolAddress((void**)&Atl, g_Attl);
    cudaGetSymbolAddress((void**)&Whh, g_Whh); cudaGetSymbolAddress((void**)&Ch, g_Ch);

    const float sscale = 22.627416997969522f;  // sqrt(512)
    const dim3 blk(256);

    // dynamic smem opt-in (host-side attr, idempotent, legal under capture)
    constexpr int SM3 = 4 * 3 * 128 * 12 * 4;   // 73728 B (3-pass, KTILE=16)
    constexpr int SM1 = 2 * 3 * 128 * 20 * 4;   // 61440 B (1-pass, KTILE=32)
    cudaFuncSetAttribute(hgemm<3, 16, false, false, true, 1, false>,
                         cudaFuncAttributeMaxDynamicSharedMemorySize, SM3);
    cudaFuncSetAttribute(hgemm<3, 16, true, false, true, 0, false>,
                         cudaFuncAttributeMaxDynamicSharedMemorySize, SM3);
    cudaFuncSetAttribute(hgemm<3, 16, false, false, true, 0, true>,
                         cudaFuncAttributeMaxDynamicSharedMemorySize, SM3);
    cudaFuncSetAttribute(hgemm<1, 32, false, true, false, 0, false>,
                         cudaFuncAttributeMaxDynamicSharedMemorySize, SM1);

    // 0) weight splits (vectorized)
    conv_split<<<256, 256>>>(Wq, Wqh, Wql, KQD * EMBED / 4);
    conv_split<<<256, 256>>>(Wk, Wkh, Wkl, KQD * EMBED / 4);
    conv_split<<<256, 256>>>(Wv, Wvh, Wvl, VDIM * EMBED / 4);
    conv_split<<<4096, 256>>>(Wh, Whh, nullptr, VOCAB * VDIM / 4);

    // 1) embedding + PE -> hi/lo
    embed_pe_kernel<<<NTOK, 128>>>(x, emb);

    // 2) QKV (3-pass), epilogue emits Q/K row hi/lo + V^T hi/lo
    {
        HG g = {};
        g.Ah[0] = g.Ah[1] = g.Ah[2] = hh;
        g.Al[0] = g.Al[1] = g.Al[2] = hl;
        g.Bh[0] = Wqh; g.Bh[1] = Wkh; g.Bh[2] = Wvh;
        g.Bl[0] = Wql; g.Bl[1] = Wkl; g.Bl[2] = Wvl;
        g.Oh[0] = Qh; g.Oh[1] = Kh; g.Oh[2] = Vth;
        g.Ol[0] = Ql; g.Ol[1] = Kl; g.Ol[2] = Vtl;
        hgemm<3, 16, false, false, true, 1, false><<<dim3(4, 32, 3), blk, SM3>>>(
            g, nullptr, EMBED, EMBED, EMBED, KQD, 1.f, nullptr);
    }

    // 3) scores = sqrt(512) * Q K^T (3-pass, causal tiles skipped)
    {
        HG g = {};
        for (int b = 0; b < NB; b++) {
            g.Ah[b] = Qh + (size_t)b * SEQ * KQD;
            g.Al[b] = Ql + (size_t)b * SEQ * KQD;
            g.Bh[b] = Kh + (size_t)b * SEQ * KQD;
            g.Bl[b] = Kl + (size_t)b * SEQ * KQD;
            g.C[b]  = S + (size_t)b * SEQ * SEQ;
        }
        hgemm<3, 16, true, false, true, 0, false><<<dim3(16, 16, NB), blk, SM3>>>(
            g, nullptr, KQD, KQD, KQD, SEQ, sscale, nullptr);
    }

    // 4) softmax -> attn hi/lo fp16
    softmax_causal_kernel<<<NTOK, 256>>>();

    // 5) ctx = attn @ V^T, balanced 256-k chunks, split-k partials
    {
        HG g = {};
        for (int b = 0; b < NB; b++) {
            g.Ah[b] = Ath + (size_t)b * SEQ * SEQ;
            g.Al[b] = Atl + (size_t)b * SEQ * SEQ;
            g.Bh[b] = Vth + (size_t)b * VDIM * SEQ;
            g.Bl[b] = Vtl + (size_t)b * VDIM * SEQ;
        }
        hgemm<3, 16, false, false, true, 0, true><<<dim3(72, 4, NB), blk, SM3>>>(
            g, nullptr, SEQ, SEQ, SEQ, 128, 1.f, Cp);
    }

    // 5b) reduce partials -> ctx fp16
    reduce_ctx<<<2048, 256>>>(Cp, Ch);

    // 6) logits = ctx @ Wh^T + bh (1-pass fp16, KTILE=32; m tiles fast for L2)
    {
        HG g = {};
        g.Ah[0] = Ch; g.Bh[0] = Whh; g.C[0] = out;
        hgemm<1, 32, false, true, false, 0, false><<<dim3(32, 250, 1), blk, SM1>>>(
            g, bh, VDIM, VDIM, VDIM, VOCAB, 1.f, nullptr);
    }
}

// round 12
// speedup vs baseline: 2.2989x; 1.0517x over previous
#include <cuda_runtime.h>
#include <cuda_fp16.h>
#include <math.h>
#include <stdint.h>

#define VOCAB 32000
#define EMBED 512
#define KQD   512
#define VDIM  512
#define NB    2
#define SEQ   2048
#define NTOK  (NB * SEQ)

// ---------------- scratch (__device__ globals; no allocation) ---------------
__device__ float  g_S[(size_t)NB * SEQ * SEQ];            // fp32 scores
__device__ __half g_hh[NTOK * EMBED],  g_hl[NTOK * EMBED];
__device__ __half g_Wqh[KQD * EMBED],  g_Wql[KQD * EMBED];
__device__ __half g_Wkh[KQD * EMBED],  g_Wkl[KQD * EMBED];
__device__ __half g_Wvh[VDIM * EMBED], g_Wvl[VDIM * EMBED];
__device__ __half g_Qh[NTOK * KQD],  g_Ql[NTOK * KQD];
__device__ __half g_Kh[NTOK * KQD],  g_Kl[NTOK * KQD];
__device__ __half g_Vth[NB * VDIM * SEQ];                 // V transposed (hi only)
__device__ __half g_Atth[(size_t)NB * SEQ * SEQ];         // attn (hi only)
__device__ __half g_Whh[(size_t)VOCAB * VDIM];
__device__ float  g_Cp[(size_t)NB * 4 * 72 * 128 * 128];  // ctx split-k partials
__device__ __half g_Ch[NTOK * VDIM];

// chunk-prefix table: S[m] = sum_{j<m} ceil((j+1)/2); S[16]=72
__device__ const int c_S[17] = {0,1,2,4,6,9,12,16,20,25,30,36,42,49,56,64,72};

struct HG {
    const __half* Ah[3]; const __half* Al[3];
    const __half* Bh[3]; const __half* Bl[3];
    float* C[3];
    __half* Oh[3]; __half* Ol[3];
};

// ---------------- helpers ----------------------------------------------------
__device__ __forceinline__ uint32_t s2u(const void* p) {
    uint32_t a;
    asm("{ .reg .u64 t; cvta.to.shared.u64 t, %1; cvt.u32.u64 %0, t; }"
        : "=r"(a) : "l"(p));
    return a;
}
__device__ __forceinline__ void cpa16(uint32_t d, const void* s) {
    asm volatile("cp.async.cg.shared.global [%0], [%1], 16;" :: "r"(d), "l"(s) : "memory");
}
__device__ __forceinline__ void cpcommit() {
    asm volatile("cp.async.commit_group;" ::: "memory");
}
template <int N> __device__ __forceinline__ void cpwait() {
    asm volatile("cp.async.wait_group %0;" :: "n"(N) : "memory");
}
__device__ __forceinline__ void mma_f16(float* acc, const uint32_t* a,
                                        const uint32_t* b) {
    asm("mma.sync.aligned.m16n8k16.row.col.f32.f16.f16.f32 "
        "{%0,%1,%2,%3}, {%4,%5,%6,%7}, {%8,%9}, {%0,%1,%2,%3};"
        : "+f"(acc[0]), "+f"(acc[1]), "+f"(acc[2]), "+f"(acc[3])
        : "r"(a[0]), "r"(a[1]), "r"(a[2]), "r"(a[3]), "r"(b[0]), "r"(b[1]));
}

// ---------------- stage 0: fp32 -> fp16 hi/lo split (vectorized) ------------
__global__ void conv_split(const float* __restrict__ src, __half* __restrict__ dh,
                           __half* __restrict__ dl, int n4) {
    const float4* s4 = (const float4*)src;
    int i = blockIdx.x * blockDim.x + threadIdx.x;
    const int stride = gridDim.x * blockDim.x;
    for (; i < n4; i += stride) {
        float4 v = s4[i];
        __half2 h0 = __floats2half2_rn(v.x, v.y);
        __half2 h1 = __floats2half2_rn(v.z, v.w);
        uint2 hp;
        hp.x = *(uint32_t*)&h0;
        hp.y = *(uint32_t*)&h1;
        *(uint2*)&dh[i * 4] = hp;
        if (dl) {
            __half2 l0 = __floats2half2_rn(v.x - __low2float(h0), v.y - __high2float(h0));
            __half2 l1 = __floats2half2_rn(v.z - __low2float(h1), v.w - __high2float(h1));
            uint2 lp;
            lp.x = *(uint32_t*)&l0;
            lp.y = *(uint32_t*)&l1;
            *(uint2*)&dl[i * 4] = lp;
        }
    }
}

// ---------------- stage 1: h = emb[x] + PE -> fp16 hi/lo --------------------
__global__ void embed_pe_kernel(const int* __restrict__ x,
                                const float* __restrict__ emb) {
    int tok = blockIdx.x;
    int s = tok & (SEQ - 1);
    const float* e = emb + (size_t)x[tok] * EMBED;
    for (int i = threadIdx.x; i < EMBED; i += blockDim.x) {
        int j = i >> 1;
        float freq = expf((float)(2 * j) * (-9.210340371976184f / (float)EMBED));
        float ang = (float)s * freq;
        float pe = (i & 1) ? cosf(ang) : sinf(ang);
        float v = e[i] + pe;
        __half h = __float2half_rn(v);
        g_hh[tok * EMBED + i] = h;
        g_hl[tok * EMBED + i] = __float2half_rn(v - __half2float(h));
    }
}

// ---------------- unified NT fp16 tensor-core GEMM ---------------------------
// All operands pre-split fp16 hi/lo in global, NT layout.
// NPASS=3: hi*hi + hi*lo + lo*hi; NPASS=1: hi*hi only.
// KTILE: k per pipeline stage (16 for 3-pass, 32 for 1-pass).
// Depth-3 cp.async pipeline, ONE __syncthreads per stage.
template <int NPASS, int KTILE, bool CAUSAL_OUT, bool BIAS, bool NXFAST, int EPI, bool CHUNK>
__global__ __launch_bounds__(256, 2)
void hgemm(HG g, const float* __restrict__ bias,
           int K, int lda, int ldb, int ldc, float scale,
           float* __restrict__ Cp) {
    constexpr int KW = KTILE / 2;            // uint32 words per row per stage
    constexpr int PW = KW + 4;               // padded row (conflict-free frags)
    constexpr int ARRS = (NPASS == 3) ? 4 : 2;
    constexpr int ABUF = 128 * PW;           // words per array per buffer
    constexpr int BUFW = ARRS * ABUF;        // words per buffer
    constexpr int CPR = KW / 4;              // 16B chunks per row
    constexpr int CPT = (128 * CPR) / 256;   // chunks per thread per array

    extern __shared__ uint32_t sm[];

    int m0, n0, kbeg, kend;
    float* Cf = nullptr;
    const int z = blockIdx.z;
    if (CHUNK) {
        const int c = blockIdx.x;
        int m = 0;
#pragma unroll
        for (int j = 1; j <= 15; j++)
            if (c >= c_S[j]) m = j;
        const int kb = c - c_S[m];
        kbeg = kb * 256;
        kend = min((m + 1) * 128, kbeg + 256);
        m0 = m * 128;
        n0 = blockIdx.y * 128;
        Cf = Cp + (size_t)((z * 4 + blockIdx.y) * 72 + c) * 16384;
    } else {
        n0 = (NXFAST ? blockIdx.x : blockIdx.y) * 128;
        m0 = (NXFAST ? blockIdx.y : blockIdx.x) * 128;
        if (CAUSAL_OUT && n0 > m0 + 127) return;
        kbeg = 0; kend = K;
        if (EPI == 0) Cf = g.C[z];
    }
    const __half* gAh = g.Ah[z];
    const __half* gBh = g.Bh[z];
    const __half* gAl = (NPASS == 3) ? g.Al[z] : nullptr;
    const __half* gBl = (NPASS == 3) ? g.Bl[z] : nullptr;

    const int tid = threadIdx.x, lane = tid & 31, wid = tid >> 5;
    const int warpM = wid >> 2, warpN = wid & 3, qr = lane >> 2, qc = lane & 3;
    const uint32_t usm = s2u(sm);

    auto fill = [&](int buf, int it) {
        const int ko = kbeg + it * KTILE;
#pragma unroll
        for (int j = 0; j < CPT; j++) {
            const int c = tid + j * 256;
            const int row = c / CPR, kc = c % CPR;
            const uint32_t d = usm + 4u * ((uint32_t)buf * BUFW + row * PW + kc * 4);
            cpa16(d, gAh + (size_t)(m0 + row) * lda + ko + kc * 8);
            cpa16(d + 4u * ABUF, gBh + (size_t)(n0 + row) * ldb + ko + kc * 8);
            if (NPASS == 3) {
                cpa16(d + 8u * ABUF, gAl + (size_t)(m0 + row) * lda + ko + kc * 8);
                cpa16(d + 12u * ABUF, gBl + (size_t)(n0 + row) * ldb + ko + kc * 8);
            }
        }
        cpcommit();
    };

    float acc[4][4][4] = {};
    const int NIT = (kend - kbeg) / KTILE;

    fill(0, 0);
    if (NIT > 1) fill(1, 1);
    for (int it = 0; it < NIT; it++) {
        const int cur = it % 3;
        if (it + 1 < NIT) cpwait<1>();   // buffer `it` complete (newest is it+1)
        else cpwait<0>();
        __syncthreads();
        if (it + 2 < NIT) fill((it + 2) % 3, it + 2);  // overwrites buf of it-1: safe post-barrier

        const uint32_t* Ab  = sm + cur * BUFW;
        const uint32_t* Bb  = Ab + ABUF;
        const uint32_t* Alb = Ab + 2 * ABUF;
        const uint32_t* Blb = Ab + 3 * ABUF;

#pragma unroll
        for (int ks = 0; ks < KTILE / 16; ks++) {
            const int kb = ks * 8;
            uint32_t bh[4][2], bl[4][2];
#pragma unroll
            for (int nt = 0; nt < 4; nt++) {
                const int n = warpN * 32 + nt * 8 + qr;
                bh[nt][0] = Bb[n * PW + kb + qc];
                bh[nt][1] = Bb[n * PW + kb + qc + 4];
                if (NPASS == 3) {
                    bl[nt][0] = Blb[n * PW + kb + qc];
                    bl[nt][1] = Blb[n * PW + kb + qc + 4];
                }
            }
#pragma unroll
            for (int mt = 0; mt < 4; mt++) {
                const int r = warpM * 64 + mt * 16 + qr;
                uint32_t ah[4] = {Ab[r * PW + kb + qc], Ab[(r + 8) * PW + kb + qc],
                                  Ab[r * PW + kb + qc + 4], Ab[(r + 8) * PW + kb + qc + 4]};
                uint32_t al[4];
                if (NPASS == 3) {
                    al[0] = Alb[r * PW + kb + qc];
                    al[1] = Alb[(r + 8) * PW + kb + qc];
                    al[2] = Alb[r * PW + kb + qc + 4];
                    al[3] = Alb[(r + 8) * PW + kb + qc + 4];
                }
#pragma unroll
                for (int nt = 0; nt < 4; nt++) {
                    mma_f16(acc[mt][nt], ah, bh[nt]);
                    if (NPASS == 3) {
                        mma_f16(acc[mt][nt], ah, bl[nt]);
                        mma_f16(acc[mt][nt], al, bh[nt]);
                    }
                }
            }
        }
    }

    // ---- epilogue ----
    if (EPI == 0) {
        const int mo = CHUNK ? 0 : m0;
        const int no = CHUNK ? 0 : n0;
        const int ld = CHUNK ? 128 : ldc;
#pragma unroll
        for (int mt = 0; mt < 4; mt++) {
            const int r = mo + warpM * 64 + mt * 16 + qr;
#pragma unroll
            for (int nt = 0; nt < 4; nt++) {
                const int lc = warpN * 32 + nt * 8 + qc * 2;
                float2 bb = BIAS ? *(const float2*)&bias[n0 + lc]
                                 : make_float2(0.f, 0.f);
                float2 v0, v1;
                v0.x = acc[mt][nt][0] * scale + bb.x;
                v0.y = acc[mt][nt][1] * scale + bb.y;
                v1.x = acc[mt][nt][2] * scale + bb.x;
                v1.y = acc[mt][nt][3] * scale + bb.y;
                *(float2*)&Cf[(size_t)r * ld + no + lc] = v0;
                *(float2*)&Cf[(size_t)(r + 8) * ld + no + lc] = v1;
            }
        }
    } else {
        __half* oh = g.Oh[z];
        __half* ol = g.Ol[z];
#pragma unroll
        for (int mt = 0; mt < 4; mt++) {
            const int r = m0 + warpM * 64 + mt * 16 + qr;
#pragma unroll
            for (int nt = 0; nt < 4; nt++) {
                const int cc = n0 + warpN * 32 + nt * 8 + qc * 2;
                __half h[4], l[4];
#pragma unroll
                for (int j = 0; j < 4; j++) {
                    float v = acc[mt][nt][j];
                    h[j] = __float2half_rn(v);
                    l[j] = __float2half_rn(v - __half2float(h[j]));
                }
                if (z < 2) {
                    *(__half2*)&oh[(size_t)r * KQD + cc] = __halves2half2(h[0], h[1]);
                    *(__half2*)&oh[(size_t)(r + 8) * KQD + cc] = __halves2half2(h[2], h[3]);
                    *(__half2*)&ol[(size_t)r * KQD + cc] = __halves2half2(l[0], l[1]);
                    *(__half2*)&ol[(size_t)(r + 8) * KQD + cc] = __halves2half2(l[2], l[3]);
                } else {
                    // V^T: hi only (ctx GEMM is 1-pass; V precision bounded by
                    // its fp16 storage either way)
#pragma unroll
                    for (int j = 0; j < 4; j++) {
                        const int rr = r + ((j >= 2) ? 8 : 0);
                        const int c = cc + (j & 1);
                        const int b = rr >> 11, s = rr & 2047;
                        const size_t o = ((size_t)b * VDIM + c) * SEQ + s;
                        oh[o] = h[j];
                    }
                }
            }
        }
    }
}

// ---------------- stage 4: causal row softmax -> fp16 attn (hi only) --------
__global__ void softmax_causal_kernel() {
    int row = blockIdx.x;
    int b = row / SEQ;
    int q = row & (SEQ - 1);
    const size_t boff = (size_t)b * SEQ * SEQ + (size_t)q * SEQ;
    float* r = g_S + boff;
    __half* oh = g_Atth + boff;
    const int len = q + 1;

    __shared__ float redm[8];
    __shared__ float reds[8];
    __shared__ float bc[2];

    float m = -INFINITY;
    for (int i = threadIdx.x; i < len; i += 256) m = fmaxf(m, r[i]);
#pragma unroll
    for (int o = 16; o; o >>= 1) m = fmaxf(m, __shfl_xor_sync(0xffffffffu, m, o));
    if ((threadIdx.x & 31) == 0) redm[threadIdx.x >> 5] = m;
    __syncthreads();
    if (threadIdx.x == 0) {
        float v = redm[0];
#pragma unroll
        for (int w = 1; w < 8; w++) v = fmaxf(v, redm[w]);
        bc[0] = v;
    }
    __syncthreads();
    const float rmax = bc[0];

    float s = 0.f;
    for (int i = threadIdx.x; i < len; i += 256) {
        float e = __expf(r[i] - rmax);
        r[i] = e;
        s += e;
    }
#pragma unroll
    for (int o = 16; o; o >>= 1) s += __shfl_xor_sync(0xffffffffu, s, o);
    if ((threadIdx.x & 31) == 0) reds[threadIdx.x >> 5] = s;
    __syncthreads();
    if (threadIdx.x == 0) {
        float v = reds[0];
#pragma unroll
        for (int w = 1; w < 8; w++) v += reds[w];
        bc[1] = 1.0f / v;
    }
    __syncthreads();
    const float inv = bc[1];

    for (int i = threadIdx.x; i < len; i += 256)
        oh[i] = __float2half_rn(r[i] * inv);
    const __half zz = __float2half_rn(0.f);
    for (int i = len + threadIdx.x; i < SEQ; i += 256) oh[i] = zz;
}

// ---------------- ctx split-k reduce -> fp16 ctx ----------------------------
__global__ void reduce_ctx(const float* __restrict__ Cp, __half* __restrict__ Ch) {
    const int idx = blockIdx.x * 256 + threadIdx.x;
    const int tok = idx >> 7;
    const int v4 = idx & 127;
    const int b = tok >> 11, t = tok & 2047;
    const int m = t >> 7, row = t & 127;
    const int n = v4 >> 5, cc = (v4 & 31) * 4;
    const int s0 = c_S[m], cnt = (m + 2) >> 1;
    float4 a = make_float4(0.f, 0.f, 0.f, 0.f);
    for (int j = 0; j < cnt; j++) {
        const size_t slot = (size_t)((b * 4 + n) * 72 + s0 + j);
        const float4 p = *(const float4*)&Cp[slot * 16384 + row * 128 + cc];
        a.x += p.x; a.y += p.y; a.z += p.z; a.w += p.w;
    }
    const size_t o = (size_t)tok * VDIM + n * 128 + cc;
    *(__half2*)&g_Ch[o] = __halves2half2(__float2half_rn(a.x), __float2half_rn(a.y));
    *(__half2*)&g_Ch[o + 2] = __halves2half2(__float2half_rn(a.z), __float2half_rn(a.w));
    (void)Ch;
}

// ---------------- launch ----------------------------------------------------
extern "C" void kernel_launch(void* const* d_in, const int* in_sizes, int n_in,
                              void* d_out, int out_size) {
    const int*   x   = (const int*)d_in[0];
    const float* emb = (const float*)d_in[1];
    const float* Wq  = (const float*)d_in[2];
    const float* Wk  = (const float*)d_in[3];
    const float* Wv  = (const float*)d_in[4];
    const float* Wh  = (const float*)d_in[5];
    const float* bh  = (const float*)d_in[6];
    float* out = (float*)d_out;

    float *S, *Cp;
    cudaGetSymbolAddress((void**)&S, g_S);
    cudaGetSymbolAddress((void**)&Cp, g_Cp);
    __half *hh, *hl, *Wqh, *Wql, *Wkh, *Wkl, *Wvh, *Wvl;
    __half *Qh, *Ql, *Kh, *Kl, *Vth, *Ath, *Whh, *Ch;
    cudaGetSymbolAddress((void**)&hh, g_hh);   cudaGetSymbolAddress((void**)&hl, g_hl);
    cudaGetSymbolAddress((void**)&Wqh, g_Wqh); cudaGetSymbolAddress((void**)&Wql, g_Wql);
    cudaGetSymbolAddress((void**)&Wkh, g_Wkh); cudaGetSymbolAddress((void**)&Wkl, g_Wkl);
    cudaGetSymbolAddress((void**)&Wvh, g_Wvh); cudaGetSymbolAddress((void**)&Wvl, g_Wvl);
    cudaGetSymbolAddress((void**)&Qh, g_Qh);   cudaGetSymbolAddress((void**)&Ql, g_Ql);
    cudaGetSymbolAddress((void**)&Kh, g_Kh);   cudaGetSymbolAddress((void**)&Kl, g_Kl);
    cudaGetSymbolAddress((void**)&Vth, g_Vth);
    cudaGetSymbolAddress((void**)&Ath, g_Atth);
    cudaGetSymbolAddress((void**)&Whh, g_Whh); cudaGetSymbolAddress((void**)&Ch, g_Ch);

    const float sscale = 22.627416997969522f;  // sqrt(512)
    const dim3 blk(256);

    // dynamic smem opt-in (host-side attr, idempotent, legal under capture)
    constexpr int SM3 = 4 * 3 * 128 * 12 * 4;   // 73728 B (3-pass, KTILE=16)
    constexpr int SM1 = 2 * 3 * 128 * 20 * 4;   // 61440 B (1-pass, KTILE=32)
    cudaFuncSetAttribute(hgemm<3, 16, false, false, true, 1, false>,
                         cudaFuncAttributeMaxDynamicSharedMemorySize, SM3);
    cudaFuncSetAttribute(hgemm<3, 16, true, false, true, 0, false>,
                         cudaFuncAttributeMaxDynamicSharedMemorySize, SM3);
    cudaFuncSetAttribute(hgemm<1, 32, false, false, true, 0, true>,
                         cudaFuncAttributeMaxDynamicSharedMemorySize, SM1);
    cudaFuncSetAttribute(hgemm<1, 32, false, true, false, 0, false>,
                         cudaFuncAttributeMaxDynamicSharedMemorySize, SM1);

    // 0) weight splits (vectorized)
    conv_split<<<256, 256>>>(Wq, Wqh, Wql, KQD * EMBED / 4);
    conv_split<<<256, 256>>>(Wk, Wkh, Wkl, KQD * EMBED / 4);
    conv_split<<<256, 256>>>(Wv, Wvh, Wvl, VDIM * EMBED / 4);
    conv_split<<<4096, 256>>>(Wh, Whh, nullptr, VOCAB * VDIM / 4);

    // 1) embedding + PE -> hi/lo
    embed_pe_kernel<<<NTOK, 128>>>(x, emb);

    // 2) QKV (3-pass), epilogue emits Q/K row hi/lo + V^T (hi only)
    {
        HG g = {};
        g.Ah[0] = g.Ah[1] = g.Ah[2] = hh;
        g.Al[0] = g.Al[1] = g.Al[2] = hl;
        g.Bh[0] = Wqh; g.Bh[1] = Wkh; g.Bh[2] = Wvh;
        g.Bl[0] = Wql; g.Bl[1] = Wkl; g.Bl[2] = Wvl;
        g.Oh[0] = Qh; g.Oh[1] = Kh; g.Oh[2] = Vth;
        g.Ol[0] = Ql; g.Ol[1] = Kl; g.Ol[2] = nullptr;
        hgemm<3, 16, false, false, true, 1, false><<<dim3(4, 32, 3), blk, SM3>>>(
            g, nullptr, EMBED, EMBED, EMBED, KQD, 1.f, nullptr);
    }

    // 3) scores = sqrt(512) * Q K^T (3-pass, causal tiles skipped)
    {
        HG g = {};
        for (int b = 0; b < NB; b++) {
            g.Ah[b] = Qh + (size_t)b * SEQ * KQD;
            g.Al[b] = Ql + (size_t)b * SEQ * KQD;
            g.Bh[b] = Kh + (size_t)b * SEQ * KQD;
            g.Bl[b] = Kl + (size_t)b * SEQ * KQD;
            g.C[b]  = S + (size_t)b * SEQ * SEQ;
        }
        hgemm<3, 16, true, false, true, 0, false><<<dim3(16, 16, NB), blk, SM3>>>(
            g, nullptr, KQD, KQD, KQD, SEQ, sscale, nullptr);
    }

    // 4) softmax -> attn fp16 (hi only)
    softmax_causal_kernel<<<NTOK, 256>>>();

    // 5) ctx = attn @ V^T — 1-pass fp16 (error bounded by fp16 ctx storage),
    //    balanced 256-k chunks, split-k partials, KTILE=32
    {
        HG g = {};
        for (int b = 0; b < NB; b++) {
            g.Ah[b] = Ath + (size_t)b * SEQ * SEQ;
            g.Bh[b] = Vth + (size_t)b * VDIM * SEQ;
        }
        hgemm<1, 32, false, false, true, 0, true><<<dim3(72, 4, NB), blk, SM1>>>(
            g, nullptr, SEQ, SEQ, SEQ, 128, 1.f, Cp);
    }

    // 5b) reduce partials -> ctx fp16
    reduce_ctx<<<2048, 256>>>(Cp, Ch);

    // 6) logits = ctx @ Wh^T + bh (1-pass fp16, KTILE=32; m tiles fast for L2)
    {
        HG g = {};
        g.Ah[0] = Ch; g.Bh[0] = Whh; g.C[0] = out;
        hgemm<1, 32, false, true, false, 0, false><<<dim3(32, 250, 1), blk, SM1>>>(
            g, bh, VDIM, VDIM, VDIM, VOCAB, 1.f, nullptr);
    }
}

// round 14
// speedup vs baseline: 2.3208x; 1.0095x over previous
#include <cuda_runtime.h>
#include <cuda_fp16.h>
#include <math.h>
#include <stdint.h>

#define VOCAB 32000
#define EMBED 512
#define KQD   512
#define VDIM  512
#define NB    2
#define SEQ   2048
#define NTOK  (NB * SEQ)

// ---------------- scratch (__device__ globals; no allocation) ---------------
__device__ float  g_S[(size_t)NB * SEQ * SEQ];            // fp32 scores
__device__ __half g_hh[NTOK * EMBED],  g_hl[NTOK * EMBED];
__device__ __half g_Wqh[KQD * EMBED],  g_Wql[KQD * EMBED];
__device__ __half g_Wkh[KQD * EMBED],  g_Wkl[KQD * EMBED];
__device__ __half g_Wvh[VDIM * EMBED], g_Wvl[VDIM * EMBED];
__device__ __half g_Qh[NTOK * KQD],  g_Ql[NTOK * KQD];
__device__ __half g_Kh[NTOK * KQD],  g_Kl[NTOK * KQD];
__device__ __half g_Vth[NB * VDIM * SEQ];                 // V transposed (hi only)
__device__ __half g_Atth[(size_t)NB * SEQ * SEQ];         // attn (hi only)
__device__ __half g_Whh[(size_t)VOCAB * VDIM];
__device__ float  g_Cp[(size_t)NB * 4 * 72 * 128 * 128];  // ctx split-k partials
__device__ __half g_Ch[NTOK * VDIM];

// chunk-prefix table: S[m] = sum_{j<m} ceil((j+1)/2); S[16]=72
__device__ const int c_S[17] = {0,1,2,4,6,9,12,16,20,25,30,36,42,49,56,64,72};

struct HG {
    const __half* Ah[3]; const __half* Al[3];
    const __half* Bh[3]; const __half* Bl[3];
    float* C[3];
    __half* Oh[3]; __half* Ol[3];
};

// ---------------- helpers ----------------------------------------------------
__device__ __forceinline__ uint32_t s2u(const void* p) {
    uint32_t a;
    asm("{ .reg .u64 t; cvta.to.shared.u64 t, %1; cvt.u32.u64 %0, t; }"
        : "=r"(a) : "l"(p));
    return a;
}
__device__ __forceinline__ void cpa16(uint32_t d, const void* s) {
    asm volatile("cp.async.cg.shared.global [%0], [%1], 16;" :: "r"(d), "l"(s) : "memory");
}
__device__ __forceinline__ void cpcommit() {
    asm volatile("cp.async.commit_group;" ::: "memory");
}
template <int N> __device__ __forceinline__ void cpwait() {
    asm volatile("cp.async.wait_group %0;" :: "n"(N) : "memory");
}
__device__ __forceinline__ void mma_f16(float* acc, const uint32_t* a,
                                        const uint32_t* b) {
    asm("mma.sync.aligned.m16n8k16.row.col.f32.f16.f16.f32 "
        "{%0,%1,%2,%3}, {%4,%5,%6,%7}, {%8,%9}, {%0,%1,%2,%3};"
        : "+f"(acc[0]), "+f"(acc[1]), "+f"(acc[2]), "+f"(acc[3])
        : "r"(a[0]), "r"(a[1]), "r"(a[2]), "r"(a[3]), "r"(b[0]), "r"(b[1]));
}

// ---------------- stage 0: fp32 -> fp16 hi/lo split (vectorized) ------------
__global__ void conv_split(const float* __restrict__ src, __half* __restrict__ dh,
                           __half* __restrict__ dl, int n4) {
    const float4* s4 = (const float4*)src;
    int i = blockIdx.x * blockDim.x + threadIdx.x;
    const int stride = gridDim.x * blockDim.x;
    for (; i < n4; i += stride) {
        float4 v = s4[i];
        __half2 h0 = __floats2half2_rn(v.x, v.y);
        __half2 h1 = __floats2half2_rn(v.z, v.w);
        uint2 hp;
        hp.x = *(uint32_t*)&h0;
        hp.y = *(uint32_t*)&h1;
        *(uint2*)&dh[i * 4] = hp;
        if (dl) {
            __half2 l0 = __floats2half2_rn(v.x - __low2float(h0), v.y - __high2float(h0));
            __half2 l1 = __floats2half2_rn(v.z - __low2float(h1), v.w - __high2float(h1));
            uint2 lp;
            lp.x = *(uint32_t*)&l0;
            lp.y = *(uint32_t*)&l1;
            *(uint2*)&dl[i * 4] = lp;
        }
    }
}

// ---------------- stage 1: h = emb[x] + PE -> fp16 hi/lo (pairwise) ---------
__global__ void embed_pe_kernel(const int* __restrict__ x,
                                const float* __restrict__ emb) {
    int tok = blockIdx.x;
    int s = tok & (SEQ - 1);
    const float2* e2 = (const float2*)(emb + (size_t)x[tok] * EMBED);
    for (int p = threadIdx.x; p < EMBED / 2; p += blockDim.x) {
        // pair (2p, 2p+1): sin and cos of the same angle
        float freq = expf((float)(2 * p) * (-9.210340371976184f / (float)EMBED));
        float ang = (float)s * freq;
        float sv, cv;
        sincosf(ang, &sv, &cv);   // full precision: score path amplifies h errors
        float2 ev = e2[p];
        float v0 = ev.x + sv;
        float v1 = ev.y + cv;
        __half h0 = __float2half_rn(v0);
        __half h1 = __float2half_rn(v1);
        *(__half2*)&g_hh[tok * EMBED + 2 * p] = __halves2half2(h0, h1);
        *(__half2*)&g_hl[tok * EMBED + 2 * p] =
            __halves2half2(__float2half_rn(v0 - __half2float(h0)),
                           __float2half_rn(v1 - __half2float(h1)));
    }
}

// ---------------- unified NT fp16 tensor-core GEMM ---------------------------
// All operands pre-split fp16 hi/lo in global, NT layout.
// NPASS=3: hi*hi + hi*lo + lo*hi; NPASS=1: hi*hi only.
// KTILE: k per pipeline stage (16 for 3-pass, 32 for 1-pass).
// Depth-3 cp.async pipeline, ONE __syncthreads per stage.
template <int NPASS, int KTILE, bool CAUSAL_OUT, bool BIAS, bool NXFAST, int EPI, bool CHUNK>
__global__ __launch_bounds__(256, 2)
void hgemm(HG g, const float* __restrict__ bias,
           int K, int lda, int ldb, int ldc, float scale,
           float* __restrict__ Cp) {
    constexpr int KW = KTILE / 2;            // uint32 words per row per stage
    constexpr int PW = KW + 4;               // padded row (conflict-free frags)
    constexpr int ARRS = (NPASS == 3) ? 4 : 2;
    constexpr int ABUF = 128 * PW;           // words per array per buffer
    constexpr int BUFW = ARRS * ABUF;        // words per buffer
    constexpr int CPR = KW / 4;              // 16B chunks per row
    constexpr int CPT = (128 * CPR) / 256;   // chunks per thread per array

    extern __shared__ uint32_t sm[];

    int m0, n0, kbeg, kend;
    float* Cf = nullptr;
    const int z = blockIdx.z;
    if (CHUNK) {
        const int c = blockIdx.x;
        int m = 0;
#pragma unroll
        for (int j = 1; j <= 15; j++)
            if (c >= c_S[j]) m = j;
        const int kb = c - c_S[m];
        kbeg = kb * 256;
        kend = min((m + 1) * 128, kbeg + 256);
        m0 = m * 128;
        n0 = blockIdx.y * 128;
        Cf = Cp + (size_t)((z * 4 + blockIdx.y) * 72 + c) * 16384;
    } else {
        n0 = (NXFAST ? blockIdx.x : blockIdx.y) * 128;
        m0 = (NXFAST ? blockIdx.y : blockIdx.x) * 128;
        if (CAUSAL_OUT && n0 > m0 + 127) return;
        kbeg = 0; kend = K;
        if (EPI == 0) Cf = g.C[z];
    }
    const __half* gAh = g.Ah[z];
    const __half* gBh = g.Bh[z];
    const __half* gAl = (NPASS == 3) ? g.Al[z] : nullptr;
    const __half* gBl = (NPASS == 3) ? g.Bl[z] : nullptr;

    const int tid = threadIdx.x, lane = tid & 31, wid = tid >> 5;
    const int warpM = wid >> 2, warpN = wid & 3, qr = lane >> 2, qc = lane & 3;
    const uint32_t usm = s2u(sm);

    auto fill = [&](int buf, int it) {
        const int ko = kbeg + it * KTILE;
#pragma unroll
        for (int j = 0; j < CPT; j++) {
            const int c = tid + j * 256;
            const int row = c / CPR, kc = c % CPR;
            const uint32_t d = usm + 4u * ((uint32_t)buf * BUFW + row * PW + kc * 4);
            cpa16(d, gAh + (size_t)(m0 + row) * lda + ko + kc * 8);
            cpa16(d + 4u * ABUF, gBh + (size_t)(n0 + row) * ldb + ko + kc * 8);
            if (NPASS == 3) {
                cpa16(d + 8u * ABUF, gAl + (size_t)(m0 + row) * lda + ko + kc * 8);
                cpa16(d + 12u * ABUF, gBl + (size_t)(n0 + row) * ldb + ko + kc * 8);
            }
        }
        cpcommit();
    };

    float acc[4][4][4] = {};
    const int NIT = (kend - kbeg) / KTILE;

    fill(0, 0);
    if (NIT > 1) fill(1, 1);
    for (int it = 0; it < NIT; it++) {
        const int cur = it % 3;
        if (it + 1 < NIT) cpwait<1>();   // buffer `it` complete (newest is it+1)
        else cpwait<0>();
        __syncthreads();
        if (it + 2 < NIT) fill((it + 2) % 3, it + 2);  // overwrites buf of it-1: safe post-barrier

        const uint32_t* Ab  = sm + cur * BUFW;
        const uint32_t* Bb  = Ab + ABUF;
        const uint32_t* Alb = Ab + 2 * ABUF;
        const uint32_t* Blb = Ab + 3 * ABUF;

#pragma unroll
        for (int ks = 0; ks < KTILE / 16; ks++) {
            const int kb = ks * 8;
            uint32_t bh[4][2], bl[4][2];
#pragma unroll
            for (int nt = 0; nt < 4; nt++) {
                const int n = warpN * 32 + nt * 8 + qr;
                bh[nt][0] = Bb[n * PW + kb + qc];
                bh[nt][1] = Bb[n * PW + kb + qc + 4];
                if (NPASS == 3) {
                    bl[nt][0] = Blb[n * PW + kb + qc];
                    bl[nt][1] = Blb[n * PW + kb + qc + 4];
                }
            }
#pragma unroll
            for (int mt = 0; mt < 4; mt++) {
                const int r = warpM * 64 + mt * 16 + qr;
                uint32_t ah[4] = {Ab[r * PW + kb + qc], Ab[(r + 8) * PW + kb + qc],
                                  Ab[r * PW + kb + qc + 4], Ab[(r + 8) * PW + kb + qc + 4]};
                uint32_t al[4];
                if (NPASS == 3) {
                    al[0] = Alb[r * PW + kb + qc];
                    al[1] = Alb[(r + 8) * PW + kb + qc];
                    al[2] = Alb[r * PW + kb + qc + 4];
                    al[3] = Alb[(r + 8) * PW + kb + qc + 4];
                }
#pragma unroll
                for (int nt = 0; nt < 4; nt++) {
                    mma_f16(acc[mt][nt], ah, bh[nt]);
                    if (NPASS == 3) {
                        mma_f16(acc[mt][nt], ah, bl[nt]);
                        mma_f16(acc[mt][nt], al, bh[nt]);
                    }
                }
            }
        }
    }

    // ---- epilogue ----
    if (EPI == 0) {
        const int mo = CHUNK ? 0 : m0;
        const int no = CHUNK ? 0 : n0;
        const int ld = CHUNK ? 128 : ldc;
#pragma unroll
        for (int mt = 0; mt < 4; mt++) {
            const int r = mo + warpM * 64 + mt * 16 + qr;
#pragma unroll
            for (int nt = 0; nt < 4; nt++) {
                const int lc = warpN * 32 + nt * 8 + qc * 2;
                float2 bb = BIAS ? *(const float2*)&bias[n0 + lc]
                                 : make_float2(0.f, 0.f);
                float2 v0, v1;
                v0.x = acc[mt][nt][0] * scale + bb.x;
                v0.y = acc[mt][nt][1] * scale + bb.y;
                v1.x = acc[mt][nt][2] * scale + bb.x;
                v1.y = acc[mt][nt][3] * scale + bb.y;
                *(float2*)&Cf[(size_t)r * ld + no + lc] = v0;
                *(float2*)&Cf[(size_t)(r + 8) * ld + no + lc] = v1;
            }
        }
    } else {
        __half* oh = g.Oh[z];
        __half* ol = g.Ol[z];
#pragma unroll
        for (int mt = 0; mt < 4; mt++) {
            const int r = m0 + warpM * 64 + mt * 16 + qr;
#pragma unroll
            for (int nt = 0; nt < 4; nt++) {
                const int cc = n0 + warpN * 32 + nt * 8 + qc * 2;
                __half h[4], l[4];
#pragma unroll
                for (int j = 0; j < 4; j++) {
                    float v = acc[mt][nt][j];
                    h[j] = __float2half_rn(v);
                    l[j] = __float2half_rn(v - __half2float(h[j]));
                }
                if (z < 2) {
                    *(__half2*)&oh[(size_t)r * KQD + cc] = __halves2half2(h[0], h[1]);
                    *(__half2*)&oh[(size_t)(r + 8) * KQD + cc] = __halves2half2(h[2], h[3]);
                    *(__half2*)&ol[(size_t)r * KQD + cc] = __halves2half2(l[0], l[1]);
                    *(__half2*)&ol[(size_t)(r + 8) * KQD + cc] = __halves2half2(l[2], l[3]);
                } else {
                    // V^T: hi only (ctx GEMM is 1-pass)
#pragma unroll
                    for (int j = 0; j < 4; j++) {
                        const int rr = r + ((j >= 2) ? 8 : 0);
                        const int c = cc + (j & 1);
                        const int b = rr >> 11, s = rr & 2047;
                        const size_t o = ((size_t)b * VDIM + c) * SEQ + s;
                        oh[o] = h[j];
                    }
                }
            }
        }
    }
}

// ---------------- stage 4: causal row softmax (register-cached) -------------
__global__ void softmax_causal_kernel() {
    int row = blockIdx.x;
    int b = row / SEQ;
    int q = row & (SEQ - 1);
    const size_t boff = (size_t)b * SEQ * SEQ + (size_t)q * SEQ;
    const float* r = g_S + boff;
    __half* oh = g_Atth + boff;
    const int len = q + 1;

    __shared__ float redm[8];
    __shared__ float reds[8];
    __shared__ float bc[2];

    // single pass: cache row in registers (8 elems/thread max)
    float rv[8];
#pragma unroll
    for (int j = 0; j < 8; j++) {
        const int i = threadIdx.x + j * 256;
        rv[j] = (i < len) ? r[i] : -INFINITY;
    }

    float m = -INFINITY;
#pragma unroll
    for (int j = 0; j < 8; j++) m = fmaxf(m, rv[j]);
#pragma unroll
    for (int o = 16; o; o >>= 1) m = fmaxf(m, __shfl_xor_sync(0xffffffffu, m, o));
    if ((threadIdx.x & 31) == 0) redm[threadIdx.x >> 5] = m;
    __syncthreads();
    if (threadIdx.x == 0) {
        float v = redm[0];
#pragma unroll
        for (int w = 1; w < 8; w++) v = fmaxf(v, redm[w]);
        bc[0] = v;
    }
    __syncthreads();
    const float rmax = bc[0];

    float s = 0.f;
#pragma unroll
    for (int j = 0; j < 8; j++) {
        const int i = threadIdx.x + j * 256;
        if (i < len) {
            rv[j] = __expf(rv[j] - rmax);
            s += rv[j];
        }
    }
#pragma unroll
    for (int o = 16; o; o >>= 1) s += __shfl_xor_sync(0xffffffffu, s, o);
    if ((threadIdx.x & 31) == 0) reds[threadIdx.x >> 5] = s;
    __syncthreads();
    if (threadIdx.x == 0) {
        float v = reds[0];
#pragma unroll
        for (int w = 1; w < 8; w++) v += reds[w];
        bc[1] = 1.0f / v;
    }
    __syncthreads();
    const float inv = bc[1];

#pragma unroll
    for (int j = 0; j < 8; j++) {
        const int i = threadIdx.x + j * 256;
        if (i < len) oh[i] = __float2half_rn(rv[j] * inv);
    }
    const __half zz = __float2half_rn(0.f);
    for (int i = len + threadIdx.x; i < SEQ; i += 256) oh[i] = zz;
}

// ---------------- ctx split-k reduce -> fp16 ctx ----------------------------
__global__ void reduce_ctx(const float* __restrict__ Cp, __half* __restrict__ Ch) {
    const int idx = blockIdx.x * 256 + threadIdx.x;
    const int tok = idx >> 7;
    const int v4 = idx & 127;
    const int b = tok >> 11, t = tok & 2047;
    const int m = t >> 7, row = t & 127;
    const int n = v4 >> 5, cc = (v4 & 31) * 4;
    const int s0 = c_S[m], cnt = (m + 2) >> 1;
    float4 a = make_float4(0.f, 0.f, 0.f, 0.f);
    for (int j = 0; j < cnt; j++) {
        const size_t slot = (size_t)((b * 4 + n) * 72 + s0 + j);
        const float4 p = *(const float4*)&Cp[slot * 16384 + row * 128 + cc];
        a.x += p.x; a.y += p.y; a.z += p.z; a.w += p.w;
    }
    const size_t o = (size_t)tok * VDIM + n * 128 + cc;
    *(__half2*)&g_Ch[o] = __halves2half2(__float2half_rn(a.x), __float2half_rn(a.y));
    *(__half2*)&g_Ch[o + 2] = __halves2half2(__float2half_rn(a.z), __float2half_rn(a.w));
    (void)Ch;
}

// ---------------- launch ----------------------------------------------------
extern "C" void kernel_launch(void* const* d_in, const int* in_sizes, int n_in,
                              void* d_out, int out_size) {
    const int*   x   = (const int*)d_in[0];
    const float* emb = (const float*)d_in[1];
    const float* Wq  = (const float*)d_in[2];
    const float* Wk  = (const float*)d_in[3];
    const float* Wv  = (const float*)d_in[4];
    const float* Wh  = (const float*)d_in[5];
    const float* bh  = (const float*)d_in[6];
    float* out = (float*)d_out;

    float *S, *Cp;
    cudaGetSymbolAddress((void**)&S, g_S);
    cudaGetSymbolAddress((void**)&Cp, g_Cp);
    __half *hh, *hl, *Wqh, *Wql, *Wkh, *Wkl, *Wvh, *Wvl;
    __half *Qh, *Ql, *Kh, *Kl, *Vth, *Ath, *Whh, *Ch;
    cudaGetSymbolAddress((void**)&hh, g_hh);   cudaGetSymbolAddress((void**)&hl, g_hl);
    cudaGetSymbolAddress((void**)&Wqh, g_Wqh); cudaGetSymbolAddress((void**)&Wql, g_Wql);
    cudaGetSymbolAddress((void**)&Wkh, g_Wkh); cudaGetSymbolAddress((void**)&Wkl, g_Wkl);
    cudaGetSymbolAddress((void**)&Wvh, g_Wvh); cudaGetSymbolAddress((void**)&Wvl, g_Wvl);
    cudaGetSymbolAddress((void**)&Qh, g_Qh);   cudaGetSymbolAddress((void**)&Ql, g_Ql);
    cudaGetSymbolAddress((void**)&Kh, g_Kh);   cudaGetSymbolAddress((void**)&Kl, g_Kl);
    cudaGetSymbolAddress((void**)&Vth, g_Vth);
    cudaGetSymbolAddress((void**)&Ath, g_Atth);
    cudaGetSymbolAddress((void**)&Whh, g_Whh); cudaGetSymbolAddress((void**)&Ch, g_Ch);

    const float sscale = 22.627416997969522f;  // sqrt(512)
    const dim3 blk(256);

    // dynamic smem opt-in (host-side attr, idempotent, legal under capture)
    constexpr int SM3 = 4 * 3 * 128 * 12 * 4;   // 73728 B (3-pass, KTILE=16)
    constexpr int SM1 = 2 * 3 * 128 * 20 * 4;   // 61440 B (1-pass, KTILE=32)
    cudaFuncSetAttribute(hgemm<3, 16, false, false, true, 1, false>,
                         cudaFuncAttributeMaxDynamicSharedMemorySize, SM3);
    cudaFuncSetAttribute(hgemm<3, 16, true, false, true, 0, false>,
                         cudaFuncAttributeMaxDynamicSharedMemorySize, SM3);
    cudaFuncSetAttribute(hgemm<1, 32, false, false, true, 0, true>,
                         cudaFuncAttributeMaxDynamicSharedMemorySize, SM1);
    cudaFuncSetAttribute(hgemm<1, 32, false, true, false, 0, false>,
                         cudaFuncAttributeMaxDynamicSharedMemorySize, SM1);

    // ---- stream fork: weight splits run concurrently with embed/QKV/scores ---
    cudaStream_t sB;
    cudaStreamCreateWithFlags(&sB, cudaStreamNonBlocking);
    cudaEvent_t evRoot, evWqkv, evWh;
    cudaEventCreateWithFlags(&evRoot, cudaEventDisableTiming);
    cudaEventCreateWithFlags(&evWqkv, cudaEventDisableTiming);
    cudaEventCreateWithFlags(&evWh, cudaEventDisableTiming);

    cudaEventRecord(evRoot, 0);
    cudaStreamWaitEvent(sB, evRoot, 0);

    // 0) weight splits on side stream
    conv_split<<<256, 256, 0, sB>>>(Wq, Wqh, Wql, KQD * EMBED / 4);
    conv_split<<<256, 256, 0, sB>>>(Wk, Wkh, Wkl, KQD * EMBED / 4);
    conv_split<<<256, 256, 0, sB>>>(Wv, Wvh, Wvl, VDIM * EMBED / 4);
    cudaEventRecord(evWqkv, sB);
    conv_split<<<4096, 256, 0, sB>>>(Wh, Whh, nullptr, VOCAB * VDIM / 4);
    cudaEventRecord(evWh, sB);

    // 1) embedding + PE -> hi/lo (main stream, concurrent with weight splits)
    embed_pe_kernel<<<NTOK, 128>>>(x, emb);

    // join: QKV needs Wq/Wk/Wv splits
    cudaStreamWaitEvent(0, evWqkv, 0);

    // 2) QKV (3-pass), epilogue emits Q/K row hi/lo + V^T (hi only)
    {
        HG g = {};
        g.Ah[0] = g.Ah[1] = g.Ah[2] = hh;
        g.Al[0] = g.Al[1] = g.Al[2] = hl;
        g.Bh[0] = Wqh; g.Bh[1] = Wkh; g.Bh[2] = Wvh;
        g.Bl[0] = Wql; g.Bl[1] = Wkl; g.Bl[2] = Wvl;
        g.Oh[0] = Qh; g.Oh[1] = Kh; g.Oh[2] = Vth;
        g.Ol[0] = Ql; g.Ol[1] = Kl; g.Ol[2] = nullptr;
        hgemm<3, 16, false, false, true, 1, false><<<dim3(4, 32, 3), blk, SM3>>>(
            g, nullptr, EMBED, EMBED, EMBED, KQD, 1.f, nullptr);
    }

    // 3) scores = sqrt(512) * Q K^T (3-pass, causal tiles skipped)
    {
        HG g = {};
        for (int b = 0; b < NB; b++) {
            g.Ah[b] = Qh + (size_t)b * SEQ * KQD;
            g.Al[b] = Ql + (size_t)b * SEQ * KQD;
            g.Bh[b] = Kh + (size_t)b * SEQ * KQD;
            g.Bl[b] = Kl + (size_t)b * SEQ * KQD;
            g.C[b]  = S + (size_t)b * SEQ * SEQ;
        }
        hgemm<3, 16, true, false, true, 0, false><<<dim3(16, 16, NB), blk, SM3>>>(
            g, nullptr, KQD, KQD, KQD, SEQ, sscale, nullptr);
    }

    // 4) softmax -> attn fp16 (register-cached, single global pass)
    softmax_causal_kernel<<<NTOK, 256>>>();

    // 5) ctx = attn @ V^T — 1-pass fp16, balanced 256-k chunks, split-k
    {
        HG g = {};
        for (int b = 0; b < NB; b++) {
            g.Ah[b] = Ath + (size_t)b * SEQ * SEQ;
            g.Bh[b] = Vth + (size_t)b * VDIM * SEQ;
        }
        hgemm<1, 32, false, false, true, 0, true><<<dim3(72, 4, NB), blk, SM1>>>(
            g, nullptr, SEQ, SEQ, SEQ, 128, 1.f, Cp);
    }

    // 5b) reduce partials -> ctx fp16
    reduce_ctx<<<2048, 256>>>(Cp, Ch);

    // join: logits needs the Wh split
    cudaStreamWaitEvent(0, evWh, 0);

    // 6) logits = ctx @ Wh^T + bh (1-pass fp16, KTILE=32; m tiles fast for L2)
    {
        HG g = {};
        g.Ah[0] = Ch; g.Bh[0] = Whh; g.C[0] = out;
        hgemm<1, 32, false, true, false, 0, false><<<dim3(32, 250, 1), blk, SM1>>>(
            g, bh, VDIM, VDIM, VDIM, VOCAB, 1.f, nullptr);
    }
}

// round 17
// speedup vs baseline: 2.3599x; 1.0168x over previous
#include <cuda_runtime.h>
#include <cuda_fp16.h>
#include <math.h>
#include <stdint.h>

#define VOCAB 32000
#define EMBED 512
#define KQD   512
#define VDIM  512
#define NB    2
#define SEQ   2048
#define NTOK  (NB * SEQ)

// ---------------- scratch (__device__ globals; no allocation) ---------------
__device__ float  g_S[(size_t)NB * SEQ * SEQ];            // fp32 scores
__device__ __half g_hh[NTOK * EMBED],  g_hl[NTOK * EMBED];
__device__ __half g_Wqh[KQD * EMBED],  g_Wql[KQD * EMBED];
__device__ __half g_Wkh[KQD * EMBED],  g_Wkl[KQD * EMBED];
__device__ __half g_Wvh[VDIM * EMBED];
__device__ __half g_Qh[NTOK * KQD],  g_Ql[NTOK * KQD];
__device__ __half g_Kh[NTOK * KQD],  g_Kl[NTOK * KQD];
__device__ __half g_Vth[NB * VDIM * SEQ];                 // V transposed (hi only)
__device__ __half g_Atth[(size_t)NB * SEQ * SEQ];         // attn (hi only)
__device__ __half g_Whh[(size_t)VOCAB * VDIM];
__device__ float  g_Cp[(size_t)NB * 4 * 72 * 128 * 128];  // ctx split-k partials
__device__ __half g_Ch[NTOK * VDIM];

// chunk-prefix table: S[m] = sum_{j<m} ceil((j+1)/2); S[16]=72
__device__ const int c_S[17] = {0,1,2,4,6,9,12,16,20,25,30,36,42,49,56,64,72};

struct HG {
    const __half* Ah[3]; const __half* Al[3];
    const __half* Bh[3]; const __half* Bl[3];
    float* C[3];
    __half* Oh[3]; __half* Ol[3];
};

// ---------------- helpers ----------------------------------------------------
__device__ __forceinline__ uint32_t s2u(const void* p) {
    uint32_t a;
    asm("{ .reg .u64 t; cvta.to.shared.u64 t, %1; cvt.u32.u64 %0, t; }"
        : "=r"(a) : "l"(p));
    return a;
}
__device__ __forceinline__ void cpa16(uint32_t d, const void* s) {
    asm volatile("cp.async.cg.shared.global [%0], [%1], 16;" :: "r"(d), "l"(s) : "memory");
}
__device__ __forceinline__ void cpcommit() {
    asm volatile("cp.async.commit_group;" ::: "memory");
}
template <int N> __device__ __forceinline__ void cpwait() {
    asm volatile("cp.async.wait_group %0;" :: "n"(N) : "memory");
}
__device__ __forceinline__ void mma_f16(float* acc, const uint32_t* a,
                                        const uint32_t* b) {
    asm("mma.sync.aligned.m16n8k16.row.col.f32.f16.f16.f32 "
        "{%0,%1,%2,%3}, {%4,%5,%6,%7}, {%8,%9}, {%0,%1,%2,%3};"
        : "+f"(acc[0]), "+f"(acc[1]), "+f"(acc[2]), "+f"(acc[3])
        : "r"(a[0]), "r"(a[1]), "r"(a[2]), "r"(a[3]), "r"(b[0]), "r"(b[1]));
}

// ---------------- stage 0: fp32 -> fp16 hi/lo split (vectorized) ------------
__global__ void conv_split(const float* __restrict__ src, __half* __restrict__ dh,
                           __half* __restrict__ dl, int n4) {
    const float4* s4 = (const float4*)src;
    int i = blockIdx.x * blockDim.x + threadIdx.x;
    const int stride = gridDim.x * blockDim.x;
    for (; i < n4; i += stride) {
        float4 v = s4[i];
        __half2 h0 = __floats2half2_rn(v.x, v.y);
        __half2 h1 = __floats2half2_rn(v.z, v.w);
        uint2 hp;
        hp.x = *(uint32_t*)&h0;
        hp.y = *(uint32_t*)&h1;
        *(uint2*)&dh[i * 4] = hp;
        if (dl) {
            __half2 l0 = __floats2half2_rn(v.x - __low2float(h0), v.y - __high2float(h0));
            __half2 l1 = __floats2half2_rn(v.z - __low2float(h1), v.w - __high2float(h1));
            uint2 lp;
            lp.x = *(uint32_t*)&l0;
            lp.y = *(uint32_t*)&l1;
            *(uint2*)&dl[i * 4] = lp;
        }
    }
}

// ---------------- stage 1: h = emb[x] + PE -> fp16 hi/lo (pairwise) ---------
__global__ void embed_pe_kernel(const int* __restrict__ x,
                                const float* __restrict__ emb) {
    int tok = blockIdx.x;
    int s = tok & (SEQ - 1);
    const float2* e2 = (const float2*)(emb + (size_t)x[tok] * EMBED);
    for (int p = threadIdx.x; p < EMBED / 2; p += blockDim.x) {
        float freq = expf((float)(2 * p) * (-9.210340371976184f / (float)EMBED));
        float ang = (float)s * freq;
        float sv, cv;
        sincosf(ang, &sv, &cv);   // full precision: score path amplifies h errors
        float2 ev = e2[p];
        float v0 = ev.x + sv;
        float v1 = ev.y + cv;
        __half h0 = __float2half_rn(v0);
        __half h1 = __float2half_rn(v1);
        *(__half2*)&g_hh[tok * EMBED + 2 * p] = __halves2half2(h0, h1);
        *(__half2*)&g_hl[tok * EMBED + 2 * p] =
            __halves2half2(__float2half_rn(v0 - __half2float(h0)),
                           __float2half_rn(v1 - __half2float(h1)));
    }
}

// ---------------- unified NT fp16 tensor-core GEMM ---------------------------
// NPASS=3: hi*hi + hi*lo + lo*hi; NPASS=1: hi*hi only.
// KTILE: k per pipeline stage (16 for 3-pass, 32 for 1-pass).
// EPI=0: fp32 C (+bias,scale). EPI=1: Q/K row-major hi/lo fp16. EPI=2: V^T hi.
// Depth-3 cp.async pipeline, ONE __syncthreads per stage.
template <int NPASS, int KTILE, bool CAUSAL_OUT, bool BIAS, bool NXFAST, int EPI, bool CHUNK>
__global__ __launch_bounds__(256, 2)
void hgemm(HG g, const float* __restrict__ bias,
           int K, int lda, int ldb, int ldc, float scale,
           float* __restrict__ Cp) {
    constexpr int KW = KTILE / 2;            // uint32 words per row per stage
    constexpr int PW = KW + 4;               // padded row (conflict-free frags)
    constexpr int ARRS = (NPASS == 3) ? 4 : 2;
    constexpr int ABUF = 128 * PW;           // words per array per buffer
    constexpr int BUFW = ARRS * ABUF;        // words per buffer
    constexpr int CPR = KW / 4;              // 16B chunks per row
    constexpr int CPT = (128 * CPR) / 256;   // chunks per thread per array

    extern __shared__ uint32_t sm[];

    int m0, n0, kbeg, kend;
    float* Cf = nullptr;
    const int z = blockIdx.z;
    if (CHUNK) {
        const int c = blockIdx.x;
        int m = 0;
#pragma unroll
        for (int j = 1; j <= 15; j++)
            if (c >= c_S[j]) m = j;
        const int kb = c - c_S[m];
        kbeg = kb * 256;
        kend = min((m + 1) * 128, kbeg + 256);
        m0 = m * 128;
        n0 = blockIdx.y * 128;
        Cf = Cp + (size_t)((z * 4 + blockIdx.y) * 72 + c) * 16384;
    } else {
        n0 = (NXFAST ? blockIdx.x : blockIdx.y) * 128;
        m0 = (NXFAST ? blockIdx.y : blockIdx.x) * 128;
        if (CAUSAL_OUT && n0 > m0 + 127) return;
        kbeg = 0; kend = K;
        if (EPI == 0) Cf = g.C[z];
    }
    const __half* gAh = g.Ah[z];
    const __half* gBh = g.Bh[z];
    const __half* gAl = (NPASS == 3) ? g.Al[z] : nullptr;
    const __half* gBl = (NPASS == 3) ? g.Bl[z] : nullptr;

    const int tid = threadIdx.x, lane = tid & 31, wid = tid >> 5;
    const int warpM = wid >> 2, warpN = wid & 3, qr = lane >> 2, qc = lane & 3;
    const uint32_t usm = s2u(sm);

    auto fill = [&](int buf, int it) {
        const int ko = kbeg + it * KTILE;
#pragma unroll
        for (int j = 0; j < CPT; j++) {
            const int c = tid + j * 256;
            const int row = c / CPR, kc = c % CPR;
            const uint32_t d = usm + 4u * ((uint32_t)buf * BUFW + row * PW + kc * 4);
            cpa16(d, gAh + (size_t)(m0 + row) * lda + ko + kc * 8);
            cpa16(d + 4u * ABUF, gBh + (size_t)(n0 + row) * ldb + ko + kc * 8);
            if (NPASS == 3) {
                cpa16(d + 8u * ABUF, gAl + (size_t)(m0 + row) * lda + ko + kc * 8);
                cpa16(d + 12u * ABUF, gBl + (size_t)(n0 + row) * ldb + ko + kc * 8);
            }
        }
        cpcommit();
    };

    float acc[4][4][4] = {};
    const int NIT = (kend - kbeg) / KTILE;

    fill(0, 0);
    if (NIT > 1) fill(1, 1);
    for (int it = 0; it < NIT; it++) {
        const int cur = it % 3;
        if (it + 1 < NIT) cpwait<1>();   // buffer `it` complete (newest is it+1)
        else cpwait<0>();
        __syncthreads();
        if (it + 2 < NIT) fill((it + 2) % 3, it + 2);  // safe post-barrier

        const uint32_t* Ab  = sm + cur * BUFW;
        const uint32_t* Bb  = Ab + ABUF;
        const uint32_t* Alb = Ab + 2 * ABUF;
        const uint32_t* Blb = Ab + 3 * ABUF;

#pragma unroll
        for (int ks = 0; ks < KTILE / 16; ks++) {
            const int kb = ks * 8;
            uint32_t bh[4][2], bl[4][2];
#pragma unroll
            for (int nt = 0; nt < 4; nt++) {
                const int n = warpN * 32 + nt * 8 + qr;
                bh[nt][0] = Bb[n * PW + kb + qc];
                bh[nt][1] = Bb[n * PW + kb + qc + 4];
                if (NPASS == 3) {
                    bl[nt][0] = Blb[n * PW + kb + qc];
                    bl[nt][1] = Blb[n * PW + kb + qc + 4];
                }
            }
#pragma unroll
            for (int mt = 0; mt < 4; mt++) {
                const int r = warpM * 64 + mt * 16 + qr;
                uint32_t ah[4] = {Ab[r * PW + kb + qc], Ab[(r + 8) * PW + kb + qc],
                                  Ab[r * PW + kb + qc + 4], Ab[(r + 8) * PW + kb + qc + 4]};
                uint32_t al[4];
                if (NPASS == 3) {
                    al[0] = Alb[r * PW + kb + qc];
                    al[1] = Alb[(r + 8) * PW + kb + qc];
                    al[2] = Alb[r * PW + kb + qc + 4];
                    al[3] = Alb[(r + 8) * PW + kb + qc + 4];
                }
#pragma unroll
                for (int nt = 0; nt < 4; nt++) {
                    mma_f16(acc[mt][nt], ah, bh[nt]);
                    if (NPASS == 3) {
                        mma_f16(acc[mt][nt], ah, bl[nt]);
                        mma_f16(acc[mt][nt], al, bh[nt]);
                    }
                }
            }
        }
    }

    // ---- epilogue ----
    if (EPI == 0) {
        const int mo = CHUNK ? 0 : m0;
        const int no = CHUNK ? 0 : n0;
        const int ld = CHUNK ? 128 : ldc;
#pragma unroll
        for (int mt = 0; mt < 4; mt++) {
            const int r = mo + warpM * 64 + mt * 16 + qr;
#pragma unroll
            for (int nt = 0; nt < 4; nt++) {
                const int lc = warpN * 32 + nt * 8 + qc * 2;
                float2 bb = BIAS ? *(const float2*)&bias[n0 + lc]
                                 : make_float2(0.f, 0.f);
                float2 v0, v1;
                v0.x = acc[mt][nt][0] * scale + bb.x;
                v0.y = acc[mt][nt][1] * scale + bb.y;
                v1.x = acc[mt][nt][2] * scale + bb.x;
                v1.y = acc[mt][nt][3] * scale + bb.y;
                *(float2*)&Cf[(size_t)r * ld + no + lc] = v0;
                *(float2*)&Cf[(size_t)(r + 8) * ld + no + lc] = v1;
            }
        }
    } else if (EPI == 1) {
        // Q/K: row-major hi/lo fp16
        __half* oh = g.Oh[z];
        __half* ol = g.Ol[z];
#pragma unroll
        for (int mt = 0; mt < 4; mt++) {
            const int r = m0 + warpM * 64 + mt * 16 + qr;
#pragma unroll
            for (int nt = 0; nt < 4; nt++) {
                const int cc = n0 + warpN * 32 + nt * 8 + qc * 2;
                __half h[4], l[4];
#pragma unroll
                for (int j = 0; j < 4; j++) {
                    float v = acc[mt][nt][j];
                    h[j] = __float2half_rn(v);
                    l[j] = __float2half_rn(v - __half2float(h[j]));
                }
                *(__half2*)&oh[(size_t)r * KQD + cc] = __halves2half2(h[0], h[1]);
                *(__half2*)&oh[(size_t)(r + 8) * KQD + cc] = __halves2half2(h[2], h[3]);
                *(__half2*)&ol[(size_t)r * KQD + cc] = __halves2half2(l[0], l[1]);
                *(__half2*)&ol[(size_t)(r + 8) * KQD + cc] = __halves2half2(l[2], l[3]);
            }
        }
    } else {
        // EPI == 2: V^T hi-only fp16 (ctx GEMM is 1-pass)
        __half* oh = g.Oh[z];
#pragma unroll
        for (int mt = 0; mt < 4; mt++) {
            const int r = m0 + warpM * 64 + mt * 16 + qr;
#pragma unroll
            for (int nt = 0; nt < 4; nt++) {
                const int cc = n0 + warpN * 32 + nt * 8 + qc * 2;
#pragma unroll
                for (int j = 0; j < 4; j++) {
                    const int rr = r + ((j >= 2) ? 8 : 0);
                    const int c = cc + (j & 1);
                    const int b = rr >> 11, s = rr & 2047;
                    const size_t o = ((size_t)b * VDIM + c) * SEQ + s;
                    oh[o] = __float2half_rn(acc[mt][nt][j]);
                }
            }
        }
    }
}

// ---------------- stage 4: causal row softmax (register-cached) -------------
__global__ void softmax_causal_kernel() {
    int row = blockIdx.x;
    int b = row / SEQ;
    int q = row & (SEQ - 1);
    const size_t boff = (size_t)b * SEQ * SEQ + (size_t)q * SEQ;
    const float* r = g_S + boff;
    __half* oh = g_Atth + boff;
    const int len = q + 1;

    __shared__ float redm[8];
    __shared__ float reds[8];
    __shared__ float bc[2];

    float rv[8];
#pragma unroll
    for (int j = 0; j < 8; j++) {
        const int i = threadIdx.x + j * 256;
        rv[j] = (i < len) ? r[i] : -INFINITY;
    }

    float m = -INFINITY;
#pragma unroll
    for (int j = 0; j < 8; j++) m = fmaxf(m, rv[j]);
#pragma unroll
    for (int o = 16; o; o >>= 1) m = fmaxf(m, __shfl_xor_sync(0xffffffffu, m, o));
    if ((threadIdx.x & 31) == 0) redm[threadIdx.x >> 5] = m;
    __syncthreads();
    if (threadIdx.x == 0) {
        float v = redm[0];
#pragma unroll
        for (int w = 1; w < 8; w++) v = fmaxf(v, redm[w]);
        bc[0] = v;
    }
    __syncthreads();
    const float rmax = bc[0];

    float s = 0.f;
#pragma unroll
    for (int j = 0; j < 8; j++) {
        const int i = threadIdx.x + j * 256;
        if (i < len) {
            rv[j] = __expf(rv[j] - rmax);
            s += rv[j];
        }
    }
#pragma unroll
    for (int o = 16; o; o >>= 1) s += __shfl_xor_sync(0xffffffffu, s, o);
    if ((threadIdx.x & 31) == 0) reds[threadIdx.x >> 5] = s;
    __syncthreads();
    if (threadIdx.x == 0) {
        float v = reds[0];
#pragma unroll
        for (int w = 1; w < 8; w++) v += reds[w];
        bc[1] = 1.0f / v;
    }
    __syncthreads();
    const float inv = bc[1];

#pragma unroll
    for (int j = 0; j < 8; j++) {
        const int i = threadIdx.x + j * 256;
        if (i < len) oh[i] = __float2half_rn(rv[j] * inv);
    }
    const __half zz = __float2half_rn(0.f);
    for (int i = len + threadIdx.x; i < SEQ; i += 256) oh[i] = zz;
}

// ---------------- ctx split-k reduce -> fp16 ctx ----------------------------
__global__ void reduce_ctx(const float* __restrict__ Cp, __half* __restrict__ Ch) {
    const int idx = blockIdx.x * 256 + threadIdx.x;
    const int tok = idx >> 7;
    const int v4 = idx & 127;
    const int b = tok >> 11, t = tok & 2047;
    const int m = t >> 7, row = t & 127;
    const int n = v4 >> 5, cc = (v4 & 31) * 4;
    const int s0 = c_S[m], cnt = (m + 2) >> 1;
    float4 a = make_float4(0.f, 0.f, 0.f, 0.f);
    for (int j = 0; j < cnt; j++) {
        const size_t slot = (size_t)((b * 4 + n) * 72 + s0 + j);
        const float4 p = *(const float4*)&Cp[slot * 16384 + row * 128 + cc];
        a.x += p.x; a.y += p.y; a.z += p.z; a.w += p.w;
    }
    const size_t o = (size_t)tok * VDIM + n * 128 + cc;
    *(__half2*)&g_Ch[o] = __halves2half2(__float2half_rn(a.x), __float2half_rn(a.y));
    *(__half2*)&g_Ch[o + 2] = __halves2half2(__float2half_rn(a.z), __float2half_rn(a.w));
    (void)Ch;
}

// ---------------- launch ----------------------------------------------------
extern "C" void kernel_launch(void* const* d_in, const int* in_sizes, int n_in,
                              void* d_out, int out_size) {
    const int*   x   = (const int*)d_in[0];
    const float* emb = (const float*)d_in[1];
    const float* Wq  = (const float*)d_in[2];
    const float* Wk  = (const float*)d_in[3];
    const float* Wv  = (const float*)d_in[4];
    const float* Wh  = (const float*)d_in[5];
    const float* bh  = (const float*)d_in[6];
    float* out = (float*)d_out;

    float *S, *Cp;
    cudaGetSymbolAddress((void**)&S, g_S);
    cudaGetSymbolAddress((void**)&Cp, g_Cp);
    __half *hh, *hl, *Wqh, *Wql, *Wkh, *Wkl, *Wvh;
    __half *Qh, *Ql, *Kh, *Kl, *Vth, *Ath, *Whh, *Ch;
    cudaGetSymbolAddress((void**)&hh, g_hh);   cudaGetSymbolAddress((void**)&hl, g_hl);
    cudaGetSymbolAddress((void**)&Wqh, g_Wqh); cudaGetSymbolAddress((void**)&Wql, g_Wql);
    cudaGetSymbolAddress((void**)&Wkh, g_Wkh); cudaGetSymbolAddress((void**)&Wkl, g_Wkl);
    cudaGetSymbolAddress((void**)&Wvh, g_Wvh);
    cudaGetSymbolAddress((void**)&Qh, g_Qh);   cudaGetSymbolAddress((void**)&Ql, g_Ql);
    cudaGetSymbolAddress((void**)&Kh, g_Kh);   cudaGetSymbolAddress((void**)&Kl, g_Kl);
    cudaGetSymbolAddress((void**)&Vth, g_Vth);
    cudaGetSymbolAddress((void**)&Ath, g_Atth);
    cudaGetSymbolAddress((void**)&Whh, g_Whh); cudaGetSymbolAddress((void**)&Ch, g_Ch);

    const float sscale = 22.627416997969522f;  // sqrt(512)
    const dim3 blk(256);

    // dynamic smem opt-in (host-side attr, idempotent, legal under capture)
    constexpr int SM3 = 4 * 3 * 128 * 12 * 4;   // 73728 B (3-pass, KTILE=16)
    constexpr int SM1 = 2 * 3 * 128 * 20 * 4;   // 61440 B (1-pass, KTILE=32)
    cudaFuncSetAttribute(hgemm<3, 16, false, false, true, 1, false>,
                         cudaFuncAttributeMaxDynamicSharedMemorySize, SM3);
    cudaFuncSetAttribute(hgemm<1, 32, false, false, true, 2, false>,
                         cudaFuncAttributeMaxDynamicSharedMemorySize, SM1);
    cudaFuncSetAttribute(hgemm<3, 16, true, false, true, 0, false>,
                         cudaFuncAttributeMaxDynamicSharedMemorySize, SM3);
    cudaFuncSetAttribute(hgemm<1, 32, false, false, true, 0, true>,
                         cudaFuncAttributeMaxDynamicSharedMemorySize, SM1);
    cudaFuncSetAttribute(hgemm<1, 32, false, true, false, 0, false>,
                         cudaFuncAttributeMaxDynamicSharedMemorySize, SM1);

    // ---- stream fork (round-14 passing topology: convs only on side stream,
    //      3 events, joins side->main only) ----------------------------------
    cudaStream_t sB;
    cudaStreamCreateWithFlags(&sB, cudaStreamNonBlocking);
    cudaEvent_t evRoot, evWqkv, evWh;
    cudaEventCreateWithFlags(&evRoot, cudaEventDisableTiming);
    cudaEventCreateWithFlags(&evWqkv, cudaEventDisableTiming);
    cudaEventCreateWithFlags(&evWh, cudaEventDisableTiming);

    cudaEventRecord(evRoot, 0);
    cudaStreamWaitEvent(sB, evRoot, 0);

    // side stream: weight splits (Wq/Wk hi+lo, Wv hi-only, then Wh hi-only)
    conv_split<<<256, 256, 0, sB>>>(Wq, Wqh, Wql, KQD * EMBED / 4);
    conv_split<<<256, 256, 0, sB>>>(Wk, Wkh, Wkl, KQD * EMBED / 4);
    conv_split<<<256, 256, 0, sB>>>(Wv, Wvh, nullptr, VDIM * EMBED / 4);
    cudaEventRecord(evWqkv, sB);
    conv_split<<<4096, 256, 0, sB>>>(Wh, Whh, nullptr, VOCAB * VDIM / 4);
    cudaEventRecord(evWh, sB);

    // main: embedding + PE -> hi/lo (concurrent with weight splits)
    embed_pe_kernel<<<NTOK, 128>>>(x, emb);

    // join: Q/K/V GEMMs need the weight splits
    cudaStreamWaitEvent(0, evWqkv, 0);

    // main: QK projections (3-pass, row hi/lo epilogue)
    {
        HG g = {};
        g.Ah[0] = g.Ah[1] = hh;
        g.Al[0] = g.Al[1] = hl;
        g.Bh[0] = Wqh; g.Bh[1] = Wkh;
        g.Bl[0] = Wql; g.Bl[1] = Wkl;
        g.Oh[0] = Qh; g.Oh[1] = Kh;
        g.Ol[0] = Ql; g.Ol[1] = Kl;
        hgemm<3, 16, false, false, true, 1, false><<<dim3(4, 32, 2), blk, SM3>>>(
            g, nullptr, EMBED, EMBED, EMBED, KQD, 1.f, nullptr);
    }

    // main: V projection (1-pass, V^T hi-only epilogue) — V error is bounded
    // by its fp16 storage; no score-path amplification applies to V.
    {
        HG g = {};
        g.Ah[0] = hh; g.Bh[0] = Wvh; g.Oh[0] = Vth;
        hgemm<1, 32, false, false, true, 2, false><<<dim3(4, 32, 1), blk, SM1>>>(
            g, nullptr, EMBED, EMBED, EMBED, KQD, 1.f, nullptr);
    }

    // main: scores = sqrt(512) * Q K^T (3-pass, causal tiles skipped)
    {
        HG g = {};
        for (int b = 0; b < NB; b++) {
            g.Ah[b] = Qh + (size_t)b * SEQ * KQD;
            g.Al[b] = Ql + (size_t)b * SEQ * KQD;
            g.Bh[b] = Kh + (size_t)b * SEQ * KQD;
            g.Bl[b] = Kl + (size_t)b * SEQ * KQD;
            g.C[b]  = S + (size_t)b * SEQ * SEQ;
        }
        hgemm<3, 16, true, false, true, 0, false><<<dim3(16, 16, NB), blk, SM3>>>(
            g, nullptr, KQD, KQD, KQD, SEQ, sscale, nullptr);
    }

    // main: softmax -> attn fp16 (register-cached, single global pass)
    softmax_causal_kernel<<<NTOK, 256>>>();

    // main: ctx = attn @ V^T (1-pass, balanced 256-k chunks, split-k)
    {
        HG g = {};
        for (int b = 0; b < NB; b++) {
            g.Ah[b] = Ath + (size_t)b * SEQ * SEQ;
            g.Bh[b] = Vth + (size_t)b * VDIM * SEQ;
        }
        hgemm<1, 32, false, false, true, 0, true><<<dim3(72, 4, NB), blk, SM1>>>(
            g, nullptr, SEQ, SEQ, SEQ, 128, 1.f, Cp);
    }

    // main: reduce partials -> ctx fp16
    reduce_ctx<<<2048, 256>>>(Cp, Ch);

    // join: logits needs the Wh split
    cudaStreamWaitEvent(0, evWh, 0);

    // main: logits = ctx @ Wh^T + bh (1-pass fp16, KTILE=32; m tiles fast)
    {
        HG g = {};
        g.Ah[0] = Ch; g.Bh[0] = Whh; g.C[0] = out;
        hgemm<1, 32, false, true, false, 0, false><<<dim3(32, 250, 1), blk, SM1>>>(
            g, bh, VDIM, VDIM, VDIM, VOCAB, 1.f, nullptr);
    }
}